// round 4
// baseline (speedup 1.0000x reference)
#include <cuda_runtime.h>
#include <cstdint>

// ---------------------------------------------------------------------------
// SpatialTransformer via mma.sync TF32 (Round 4)
//  - All operands pre-rounded to tf32 (cvt.rna) once -> mainloop has NO cvt
//  - cp.async.cg double-buffered SMEM (raw bit copy), ldmatrix.x4 fragments
//  - CTA tile 128x256, 8 warps x (64x64), m16n8k8.tf32
//  - register-resident softmax, direct-STG fused epilogues
// Dataflow:
//   xt,cet,Wqt,Wkt,Wvt,Wot = rna(inputs)
//   Q  = xt @ Wqt^T + bq      (store rna)     NT, bias-N
//   K  = cet@ Wkt^T + bk      (store rna)     NT, bias-N
//   Vt = Wvt@ cet^T + bv      (store rna)     NT, bias-M -> [C, B*SKV]
//   S  = (Q @ K^T)/32                          NT, batched
//   P  = softmax_rows(S)      (store rna)
//   At = P @ Vt^T + x         (store rna)     NT, batched, +Add(raw x)
//   out= At @ Wot^T + bo                       NT, bias-N
// ---------------------------------------------------------------------------

#define Cdim  1024
#define Bdim  4
#define SQdim 2048
#define SKVdim 2048

__device__ float g_Q  [(long long)Bdim * SQdim  * Cdim];
__device__ float g_K  [(long long)Bdim * SKVdim * Cdim];
__device__ float g_Vt [(long long)Cdim * Bdim  * SKVdim];
__device__ float g_S  [(long long)Bdim * SQdim  * SKVdim];
__device__ float g_At [(long long)Bdim * SQdim  * Cdim];
__device__ float g_xt [(long long)Bdim * SQdim  * Cdim];
__device__ float g_cet[(long long)Bdim * SKVdim * Cdim];
__device__ float g_Wqt[(long long)Cdim * Cdim];
__device__ float g_Wkt[(long long)Cdim * Cdim];
__device__ float g_Wvt[(long long)Cdim * Cdim];
__device__ float g_Wot[(long long)Cdim * Cdim];

__device__ __forceinline__ float f2tf(float f){
    uint32_t r; asm("cvt.rna.tf32.f32 %0, %1;" : "=r"(r) : "f"(f));
    return __uint_as_float(r);
}

__device__ __forceinline__ void mma8(float* d, const uint32_t* a, const uint32_t* b){
    asm volatile("mma.sync.aligned.m16n8k8.row.col.f32.tf32.tf32.f32 "
        "{%0,%1,%2,%3}, {%4,%5,%6,%7}, {%8,%9}, {%0,%1,%2,%3};"
        : "+f"(d[0]), "+f"(d[1]), "+f"(d[2]), "+f"(d[3])
        : "r"(a[0]), "r"(a[1]), "r"(a[2]), "r"(a[3]), "r"(b[0]), "r"(b[1]));
}

#define LDM4(r0,r1,r2,r3,addr) \
  asm volatile("ldmatrix.sync.aligned.m8n8.x4.shared.b16 {%0,%1,%2,%3}, [%4];" \
    : "=r"(r0),"=r"(r1),"=r"(r2),"=r"(r3) : "r"(addr))

#define CPA16(dst, src) \
  asm volatile("cp.async.cg.shared.global [%0], [%1], 16;" :: "r"(dst), "l"(src))
#define CPA_COMMIT() asm volatile("cp.async.commit_group;" ::: "memory")
#define CPA_WAIT1()  asm volatile("cp.async.wait_group 1;" ::: "memory")
#define CPA_WAIT0()  asm volatile("cp.async.wait_group 0;" ::: "memory")

// SMEM (floats): A tiles 128x32 @ stride 36, B tiles 256x32 @ stride 36
#define TSTR 36
#define A0F 0
#define A1F 4608
#define B0F 9216
#define B1F 18432
#define SMEM_BYTES 110592   // 27648 floats

// D[128 x 256] tile of: scale*(A @ B^T) [+bias_N|+bias_M] [+Add] [rna-rounded]
// A: [*,K] row-major lda; B: [*,K] row-major ldb; C row-major ldc. K%32==0.
template<bool BN_, bool BM_, bool ADD_, bool RND_>
__global__ __launch_bounds__(256, 1)
void gemm_mma(const float* __restrict__ A, const float* __restrict__ B,
              const float* __restrict__ bias, const float* __restrict__ Add,
              float* __restrict__ C,
              int lda, int ldb, int ldc, int NK,
              long long sA, long long sB, long long sC, long long sAdd,
              float scale)
{
    extern __shared__ float sm[];
    uint32_t sbase;
    asm("{ .reg .u64 t; cvta.to.shared.u64 t, %1; cvt.u32.u64 %0, t; }"
        : "=r"(sbase) : "l"(sm));

    const int tid = threadIdx.x, wid = tid >> 5, lane = tid & 31;

    A += (long long)blockIdx.z * sA;
    B += (long long)blockIdx.z * sB;
    C += (long long)blockIdx.z * sC;
    if (ADD_) Add += (long long)blockIdx.z * sAdd;

    const int m0 = blockIdx.y * 128;
    const int n0 = blockIdx.x * 256;

    // ---- cp.async loader mapping ----
    const int lrow = tid >> 1;
    const int lcol = (tid & 1) * 16;
    const float* ap  = A + (long long)(m0 + lrow) * lda + lcol;
    const float* bp0 = B + (long long)(n0 + lrow) * ldb + lcol;
    const float* bp1 = bp0 + (long long)128 * ldb;
    const uint32_t a_st = sbase + (lrow * TSTR + lcol) * 4;
    const uint32_t b_st0 = sbase + B0F * 4 + (lrow * TSTR + lcol) * 4;
    const uint32_t b_st1 = b_st0 + 128 * TSTR * 4;
    const uint32_t abufs[2] = { a_st,  a_st  + A1F * 4 };
    const uint32_t bbufs0[2] = { b_st0, b_st0 + (B1F - B0F) * 4 };
    const uint32_t bbufs1[2] = { b_st1, b_st1 + (B1F - B0F) * 4 };

    // ---- warp/fragment mapping ----
    const int wm = (wid & 1) * 64;
    const int wn = (wid >> 1) * 64;
    const int qr = lane >> 2, qc = lane & 3;
    // ldmatrix per-lane source rows/cols
    const uint32_t a_frag = sbase +
        (((wm + (lane & 15)) * TSTR + (lane >> 4) * 4) * 4);
    const uint32_t b_frag = sbase + B0F * 4 +
        (((wn + (lane & 7) + ((lane >> 4) << 3)) * TSTR + ((lane >> 3) & 1) * 4) * 4);

    float acc[4][8][4];
    #pragma unroll
    for (int mi = 0; mi < 4; mi++)
        #pragma unroll
        for (int nj = 0; nj < 8; nj++)
            #pragma unroll
            for (int j = 0; j < 4; j++) acc[mi][nj][j] = 0.f;

    // ---- prologue: issue k=0 into buf 0 ----
    #pragma unroll
    for (int i = 0; i < 4; i++) CPA16(abufs[0] + i * 16, ap + i * 4);
    #pragma unroll
    for (int i = 0; i < 4; i++) CPA16(bbufs0[0] + i * 16, bp0 + i * 4);
    #pragma unroll
    for (int i = 0; i < 4; i++) CPA16(bbufs1[0] + i * 16, bp1 + i * 4);
    CPA_COMMIT();

    for (int k = 0; k < NK; k++) {
        const int buf = k & 1;
        if (k + 1 < NK) {
            const int nb = buf ^ 1;
            const int k0 = (k + 1) * 32;
            #pragma unroll
            for (int i = 0; i < 4; i++) CPA16(abufs[nb] + i * 16, ap + k0 + i * 4);
            #pragma unroll
            for (int i = 0; i < 4; i++) CPA16(bbufs0[nb] + i * 16, bp0 + k0 + i * 4);
            #pragma unroll
            for (int i = 0; i < 4; i++) CPA16(bbufs1[nb] + i * 16, bp1 + k0 + i * 4);
            CPA_COMMIT();
            CPA_WAIT1();
        } else {
            CPA_WAIT0();
        }
        __syncthreads();

        const uint32_t af = a_frag + buf * (A1F * 4);
        const uint32_t bf = b_frag + buf * ((B1F - B0F) * 4);
        #pragma unroll
        for (int s = 0; s < 4; s++) {
            uint32_t afr[4][4];
            #pragma unroll
            for (int mi = 0; mi < 4; mi++)
                LDM4(afr[mi][0], afr[mi][1], afr[mi][2], afr[mi][3],
                     af + mi * (16 * TSTR * 4) + s * 32);
            uint32_t bfr[8][2];
            #pragma unroll
            for (int nj2 = 0; nj2 < 4; nj2++) {
                uint32_t t0, t1, t2, t3;
                LDM4(t0, t1, t2, t3, bf + nj2 * (16 * TSTR * 4) + s * 32);
                bfr[nj2 * 2][0] = t0;     bfr[nj2 * 2][1] = t1;
                bfr[nj2 * 2 + 1][0] = t2; bfr[nj2 * 2 + 1][1] = t3;
            }
            #pragma unroll
            for (int mi = 0; mi < 4; mi++)
                #pragma unroll
                for (int nj = 0; nj < 8; nj++)
                    mma8(acc[mi][nj], afr[mi], bfr[nj]);
        }
        __syncthreads();
    }

    // ---- epilogue: direct STG.64 with fused scale/bias/residual/rounding ----
    #pragma unroll
    for (int mi = 0; mi < 4; mi++) {
        #pragma unroll
        for (int h = 0; h < 2; h++) {
            const long long gm = m0 + wm + mi * 16 + qr + h * 8;
            float bm = 0.f;
            if (BM_) bm = bias[gm];
            #pragma unroll
            for (int nj = 0; nj < 8; nj++) {
                const int gn = n0 + wn + nj * 8 + qc * 2;
                float vx = acc[mi][nj][h * 2 + 0] * scale;
                float vy = acc[mi][nj][h * 2 + 1] * scale;
                if (BN_) { const float2 bb = *(const float2*)(bias + gn); vx += bb.x; vy += bb.y; }
                if (BM_) { vx += bm; vy += bm; }
                if (ADD_) {
                    const float2 ad = *(const float2*)(Add + gm * ldc + gn);
                    vx += ad.x; vy += ad.y;
                }
                if (RND_) { vx = f2tf(vx); vy = f2tf(vy); }
                *(float2*)(C + gm * ldc + gn) = make_float2(vx, vy);
            }
        }
    }
}

// elementwise fp32 -> tf32(rna), float4 vectorized
__global__ __launch_bounds__(256)
void cvt_tf32(const float* __restrict__ src, float* __restrict__ dst, int n4)
{
    int i = blockIdx.x * 256 + threadIdx.x;
    if (i < n4) {
        float4 v = ((const float4*)src)[i];
        v.x = f2tf(v.x); v.y = f2tf(v.y); v.z = f2tf(v.z); v.w = f2tf(v.w);
        ((float4*)dst)[i] = v;
    }
}

// register-resident row softmax (2048 cols, 256 threads, 8 floats/thread),
// output rounded to tf32.
__global__ __launch_bounds__(256)
void softmax_reg(float* __restrict__ S)
{
    float4* p = (float4*)(S + (long long)blockIdx.x * SKVdim);
    const int tid = threadIdx.x, wid = tid >> 5, lane = tid & 31;
    __shared__ float red[8];

    float4 a = p[tid], b = p[tid + 256];
    float m = fmaxf(fmaxf(fmaxf(a.x, a.y), fmaxf(a.z, a.w)),
                    fmaxf(fmaxf(b.x, b.y), fmaxf(b.z, b.w)));
    #pragma unroll
    for (int o = 16; o > 0; o >>= 1) m = fmaxf(m, __shfl_xor_sync(~0u, m, o));
    if (lane == 0) red[wid] = m;
    __syncthreads();
    m = red[0];
    #pragma unroll
    for (int w = 1; w < 8; w++) m = fmaxf(m, red[w]);
    __syncthreads();

    a.x = __expf(a.x - m); a.y = __expf(a.y - m); a.z = __expf(a.z - m); a.w = __expf(a.w - m);
    b.x = __expf(b.x - m); b.y = __expf(b.y - m); b.z = __expf(b.z - m); b.w = __expf(b.w - m);
    float s = a.x + a.y + a.z + a.w + b.x + b.y + b.z + b.w;
    #pragma unroll
    for (int o = 16; o > 0; o >>= 1) s += __shfl_xor_sync(~0u, s, o);
    if (lane == 0) red[wid] = s;
    __syncthreads();
    s = red[0] + red[1] + red[2] + red[3] + red[4] + red[5] + red[6] + red[7];

    const float inv = 1.0f / s;
    a.x = f2tf(a.x * inv); a.y = f2tf(a.y * inv); a.z = f2tf(a.z * inv); a.w = f2tf(a.w * inv);
    b.x = f2tf(b.x * inv); b.y = f2tf(b.y * inv); b.z = f2tf(b.z * inv); b.w = f2tf(b.w * inv);
    p[tid] = a; p[tid + 256] = b;
}

extern "C" void kernel_launch(void* const* d_in, const int* in_sizes, int n_in,
                              void* d_out, int out_size)
{
    const float* x  = (const float*)d_in[0];
    const float* ce = (const float*)d_in[1];
    const float* Wq = (const float*)d_in[2];
    const float* bq = (const float*)d_in[3];
    const float* Wk = (const float*)d_in[4];
    const float* bk = (const float*)d_in[5];
    const float* Wv = (const float*)d_in[6];
    const float* bv = (const float*)d_in[7];
    const float* Wo = (const float*)d_in[8];
    const float* bo = (const float*)d_in[9];
    float* out = (float*)d_out;

    float *Q, *K, *Vt, *S, *At, *xt, *cet, *Wqt, *Wkt, *Wvt, *Wot;
    cudaGetSymbolAddress((void**)&Q,   g_Q);
    cudaGetSymbolAddress((void**)&K,   g_K);
    cudaGetSymbolAddress((void**)&Vt,  g_Vt);
    cudaGetSymbolAddress((void**)&S,   g_S);
    cudaGetSymbolAddress((void**)&At,  g_At);
    cudaGetSymbolAddress((void**)&xt,  g_xt);
    cudaGetSymbolAddress((void**)&cet, g_cet);
    cudaGetSymbolAddress((void**)&Wqt, g_Wqt);
    cudaGetSymbolAddress((void**)&Wkt, g_Wkt);
    cudaGetSymbolAddress((void**)&Wvt, g_Wvt);
    cudaGetSymbolAddress((void**)&Wot, g_Wot);

    cudaFuncSetAttribute(gemm_mma<true ,false,false,true >, cudaFuncAttributeMaxDynamicSharedMemorySize, SMEM_BYTES);
    cudaFuncSetAttribute(gemm_mma<false,true ,false,true >, cudaFuncAttributeMaxDynamicSharedMemorySize, SMEM_BYTES);
    cudaFuncSetAttribute(gemm_mma<false,false,false,false>, cudaFuncAttributeMaxDynamicSharedMemorySize, SMEM_BYTES);
    cudaFuncSetAttribute(gemm_mma<false,false,true ,true >, cudaFuncAttributeMaxDynamicSharedMemorySize, SMEM_BYTES);
    cudaFuncSetAttribute(gemm_mma<true ,false,false,false>, cudaFuncAttributeMaxDynamicSharedMemorySize, SMEM_BYTES);

    const int M = Bdim * SQdim;            // 8192
    dim3 blk(256);
    const int actN4 = M * Cdim / 4;        // 2097152
    const int wN4   = Cdim * Cdim / 4;     // 262144

    // 0: pre-round inputs to tf32
    cvt_tf32<<<(actN4 + 255) / 256, blk>>>(x,  xt,  actN4);
    cvt_tf32<<<(actN4 + 255) / 256, blk>>>(ce, cet, actN4);
    cvt_tf32<<<(wN4 + 255) / 256, blk>>>(Wq, Wqt, wN4);
    cvt_tf32<<<(wN4 + 255) / 256, blk>>>(Wk, Wkt, wN4);
    cvt_tf32<<<(wN4 + 255) / 256, blk>>>(Wv, Wvt, wN4);
    cvt_tf32<<<(wN4 + 255) / 256, blk>>>(Wo, Wot, wN4);

    // Q = xt @ Wqt^T + bq   (rounded)
    gemm_mma<true,false,false,true><<<dim3(Cdim/256, M/128, 1), blk, SMEM_BYTES>>>(
        xt, Wqt, bq, nullptr, Q, Cdim, Cdim, Cdim, Cdim/32, 0,0,0,0, 1.0f);
    // K = cet @ Wkt^T + bk  (rounded)
    gemm_mma<true,false,false,true><<<dim3(Cdim/256, M/128, 1), blk, SMEM_BYTES>>>(
        cet, Wkt, bk, nullptr, K, Cdim, Cdim, Cdim, Cdim/32, 0,0,0,0, 1.0f);
    // Vt = Wvt @ cet^T + bv ([C, B*SKV], row-bias, rounded)
    gemm_mma<false,true,false,true><<<dim3(M/256, Cdim/128, 1), blk, SMEM_BYTES>>>(
        Wvt, cet, bv, nullptr, Vt, Cdim, Cdim, M, Cdim/32, 0,0,0,0, 1.0f);
    // S = (Q @ K^T) / 32    (batched, raw fp32 out)
    gemm_mma<false,false,false,false><<<dim3(SKVdim/256, SQdim/128, Bdim), blk, SMEM_BYTES>>>(
        Q, K, nullptr, nullptr, S, Cdim, Cdim, SKVdim, Cdim/32,
        (long long)SQdim*Cdim, (long long)SKVdim*Cdim, (long long)SQdim*SKVdim, 0, 0.03125f);
    // P = softmax(S)        (rounded)
    softmax_reg<<<Bdim * SQdim, blk>>>(S);
    // At = P @ Vt^T + x     (batched, residual raw x, rounded)
    gemm_mma<false,false,true,true><<<dim3(Cdim/256, SQdim/128, Bdim), blk, SMEM_BYTES>>>(
        S, Vt, nullptr, x, At, SKVdim, M, Cdim, SKVdim/32,
        (long long)SQdim*SKVdim, (long long)SKVdim, (long long)SQdim*Cdim,
        (long long)SQdim*Cdim, 1.0f);
    // out = At @ Wot^T + bo (raw fp32 out)
    gemm_mma<true,false,false,false><<<dim3(Cdim/256, M/128, 1), blk, SMEM_BYTES>>>(
        At, Wot, bo, nullptr, out, Cdim, Cdim, Cdim, Cdim/32, 0,0,0,0, 1.0f);
}

// round 5
// speedup vs baseline: 1.4401x; 1.4401x over previous
#include <cuda_runtime.h>
#include <cuda_fp16.h>
#include <cstdint>

// ---------------------------------------------------------------------------
// SpatialTransformer, fp16 tensor-core attention path + tf32 output proj (R5)
//   xh,ceh,Wqh,Wkh,Wvh = fp16(inputs);  Wot = tf32(Wo)
//   Qh  = xh @ Wqh^T + bq            fp16 gemm, half out, bias-N
//   Kh  = ceh@ Wkh^T + bk            fp16 gemm, half out, bias-N
//   Vth = Wvh@ ceh^T + bv            fp16 gemm, half out, bias-M -> [C, B*SKV]
//   Sh  = (Qh @ Kh^T)/32             fp16 gemm, half out, batched
//   Ph  = softmax_rows(Sh)           half in/out
//   At  = Ph @ Vth^T + x             fp16 gemm, FLOAT out (rna/tf32), +Add
//   out = At @ Wot^T + bo            tf32 gemm, float out
// GEMM kernel: 128 threads (4 warps), CTA 128x128, warp 64x64,
//   BK = 128 bytes (64 halfs / 32 floats), double-buffered cp.async,
//   ldmatrix.x4 fragments, 2 CTAs/SM.
// ---------------------------------------------------------------------------

#define Cdim  1024
#define Bdim  4
#define SQdim 2048
#define SKVdim 2048
#define Mtot  (Bdim * SQdim)            // 8192

__device__ __half g_xh [(long long)Mtot * Cdim];
__device__ __half g_ceh[(long long)Mtot * Cdim];
__device__ __half g_Wqh[(long long)Cdim * Cdim];
__device__ __half g_Wkh[(long long)Cdim * Cdim];
__device__ __half g_Wvh[(long long)Cdim * Cdim];
__device__ float  g_Wot[(long long)Cdim * Cdim];
__device__ __half g_Qh [(long long)Mtot * Cdim];
__device__ __half g_Kh [(long long)Mtot * Cdim];
__device__ __half g_Vth[(long long)Cdim * Mtot];
__device__ __half g_Sh [(long long)Bdim * SQdim * SKVdim];
__device__ float  g_At [(long long)Mtot * Cdim];

__device__ __forceinline__ float f2tf(float f){
    uint32_t r; asm("cvt.rna.tf32.f32 %0, %1;" : "=r"(r) : "f"(f));
    return __uint_as_float(r);
}

__device__ __forceinline__ void mma_f16(float* d, const uint32_t* a, const uint32_t* b){
    asm volatile("mma.sync.aligned.m16n8k16.row.col.f32.f16.f16.f32 "
        "{%0,%1,%2,%3}, {%4,%5,%6,%7}, {%8,%9}, {%0,%1,%2,%3};"
        : "+f"(d[0]), "+f"(d[1]), "+f"(d[2]), "+f"(d[3])
        : "r"(a[0]), "r"(a[1]), "r"(a[2]), "r"(a[3]), "r"(b[0]), "r"(b[1]));
}
__device__ __forceinline__ void mma_tf(float* d, const uint32_t* a, const uint32_t* b){
    asm volatile("mma.sync.aligned.m16n8k8.row.col.f32.tf32.tf32.f32 "
        "{%0,%1,%2,%3}, {%4,%5,%6,%7}, {%8,%9}, {%0,%1,%2,%3};"
        : "+f"(d[0]), "+f"(d[1]), "+f"(d[2]), "+f"(d[3])
        : "r"(a[0]), "r"(a[1]), "r"(a[2]), "r"(a[3]), "r"(b[0]), "r"(b[1]));
}

#define LDM4(r0,r1,r2,r3,addr) \
  asm volatile("ldmatrix.sync.aligned.m8n8.x4.shared.b16 {%0,%1,%2,%3}, [%4];" \
    : "=r"(r0),"=r"(r1),"=r"(r2),"=r"(r3) : "r"(addr))

#define CPA16(dst, src) \
  asm volatile("cp.async.cg.shared.global [%0], [%1], 16;" :: "r"(dst), "l"(src))
#define CPA_COMMIT() asm volatile("cp.async.commit_group;" ::: "memory")
#define CPA_WAIT1()  asm volatile("cp.async.wait_group 1;" ::: "memory")
#define CPA_WAIT0()  asm volatile("cp.async.wait_group 0;" ::: "memory")

// Tile geometry (bytes): 128 rows x (128B data + 16B pad) = 18432 B per tile
#define RSTR 144
#define TILEB 18432
#define BUFB  36864          // A+B per buffer
#define SMEM_BYTES 73728

// D[128x128] tile of scale*(A @ B^T) [+biasN|+biasM] [+Add] [rna]
// F16: elements are half, BK=64;  else float(tf32 bits), BK=32.
// A: [*,K] row-major lda; B: [*,K] row-major ldb (element units). K%BK==0.
template<bool F16, bool HOUT, bool BN_, bool BM_, bool ADD_, bool RND_>
__global__ __launch_bounds__(128, 2)
void gemm_k(const void* __restrict__ A_, const void* __restrict__ B_,
            const float* __restrict__ bias, const float* __restrict__ Add,
            void* __restrict__ C_,
            int lda, int ldb, int ldc, int NK,
            long long sA, long long sB, long long sC, long long sAdd,
            float scale)
{
    using TI = typename std::conditional<F16, __half, float>::type;
    const int EPC = F16 ? 8 : 4;      // elements per 16B chunk
    const int BKE = F16 ? 64 : 32;    // elements per k-tile

    extern __shared__ char smem[];
    uint32_t sbase;
    asm("{ .reg .u64 t; cvta.to.shared.u64 t, %1; cvt.u32.u64 %0, t; }"
        : "=r"(sbase) : "l"(smem));

    const int tid = threadIdx.x, wid = tid >> 5, lane = tid & 31;

    const TI* A = (const TI*)A_ + (long long)blockIdx.z * sA;
    const TI* B = (const TI*)B_ + (long long)blockIdx.z * sB;
    if (ADD_) Add += (long long)blockIdx.z * sAdd;

    const int m0 = blockIdx.y * 128;
    const int n0 = blockIdx.x * 128;

    // ---- cp.async loader: thread = one row of A and one row of B, 8 chunks each ----
    const TI* ap = A + (long long)(m0 + tid) * lda;
    const TI* bp = B + (long long)(n0 + tid) * ldb;
    const uint32_t aSt = sbase + tid * RSTR;
    const uint32_t bSt = sbase + TILEB + tid * RSTR;

    // ---- warp/fragment mapping: 4 warps, 64x64 each ----
    const int wm = (wid & 1) * 64;
    const int wn = (wid >> 1) * 64;
    const int qr = lane >> 2, qc = lane & 3;
    uint32_t aF[4], bF[4];
    #pragma unroll
    for (int mi = 0; mi < 4; mi++)
        aF[mi] = sbase + (wm + mi * 16 + (lane & 15)) * RSTR + (lane >> 4) * 16;
    #pragma unroll
    for (int nt = 0; nt < 4; nt++)
        bF[nt] = sbase + TILEB +
                 (wn + nt * 16 + (lane & 7) + ((lane >> 4) << 3)) * RSTR +
                 ((lane >> 3) & 1) * 16;

    float acc[4][8][4];
    #pragma unroll
    for (int mi = 0; mi < 4; mi++)
        #pragma unroll
        for (int nj = 0; nj < 8; nj++)
            #pragma unroll
            for (int j = 0; j < 4; j++) acc[mi][nj][j] = 0.f;

    // ---- prologue: k-tile 0 -> buffer 0 ----
    #pragma unroll
    for (int i = 0; i < 8; i++) CPA16(aSt + i * 16, ap + i * EPC);
    #pragma unroll
    for (int i = 0; i < 8; i++) CPA16(bSt + i * 16, bp + i * EPC);
    CPA_COMMIT();

    for (int k = 0; k < NK; k++) {
        const int buf = k & 1;
        if (k + 1 < NK) {
            const uint32_t nb = (buf ^ 1) * BUFB;
            const int k0 = (k + 1) * BKE;
            #pragma unroll
            for (int i = 0; i < 8; i++) CPA16(aSt + nb + i * 16, ap + k0 + i * EPC);
            #pragma unroll
            for (int i = 0; i < 8; i++) CPA16(bSt + nb + i * 16, bp + k0 + i * EPC);
            CPA_COMMIT();
            CPA_WAIT1();
        } else {
            CPA_WAIT0();
        }
        __syncthreads();

        const uint32_t bo = buf * BUFB;
        #pragma unroll
        for (int s = 0; s < 4; s++) {
            uint32_t afr[4][4];
            #pragma unroll
            for (int mi = 0; mi < 4; mi++)
                LDM4(afr[mi][0], afr[mi][1], afr[mi][2], afr[mi][3],
                     aF[mi] + bo + s * 32);
            uint32_t bfr[8][2];
            #pragma unroll
            for (int nt = 0; nt < 4; nt++) {
                uint32_t t0, t1, t2, t3;
                LDM4(t0, t1, t2, t3, bF[nt] + bo + s * 32);
                bfr[nt * 2][0] = t0;     bfr[nt * 2][1] = t1;
                bfr[nt * 2 + 1][0] = t2; bfr[nt * 2 + 1][1] = t3;
            }
            #pragma unroll
            for (int mi = 0; mi < 4; mi++)
                #pragma unroll
                for (int nj = 0; nj < 8; nj++) {
                    if (F16) mma_f16(acc[mi][nj], afr[mi], bfr[nj]);
                    else     mma_tf (acc[mi][nj], afr[mi], bfr[nj]);
                }
        }
        __syncthreads();
    }

    // ---- epilogue: direct stores, fused scale/bias/residual/rounding ----
    #pragma unroll
    for (int mi = 0; mi < 4; mi++) {
        #pragma unroll
        for (int h = 0; h < 2; h++) {
            const long long gm = m0 + wm + mi * 16 + qr + h * 8;
            float bm = 0.f;
            if (BM_) bm = bias[gm];
            #pragma unroll
            for (int nj = 0; nj < 8; nj++) {
                const int gn = n0 + wn + nj * 8 + qc * 2;
                float vx = acc[mi][nj][h * 2 + 0] * scale;
                float vy = acc[mi][nj][h * 2 + 1] * scale;
                if (BN_) { const float2 bb = *(const float2*)(bias + gn); vx += bb.x; vy += bb.y; }
                if (BM_) { vx += bm; vy += bm; }
                if (ADD_) {
                    const float2 ad = *(const float2*)(Add + gm * ldc + gn);
                    vx += ad.x; vy += ad.y;
                }
                if (HOUT) {
                    *(half2*)((__half*)C_ + (long long)blockIdx.z * sC + gm * ldc + gn) =
                        __floats2half2_rn(vx, vy);
                } else {
                    if (RND_) { vx = f2tf(vx); vy = f2tf(vy); }
                    *(float2*)((float*)C_ + (long long)blockIdx.z * sC + gm * ldc + gn) =
                        make_float2(vx, vy);
                }
            }
        }
    }
}

// fp32 -> fp16, 8 elems/thread
__global__ __launch_bounds__(256)
void f32_to_f16(const float* __restrict__ src, __half* __restrict__ dst, int n8)
{
    int i = blockIdx.x * 256 + threadIdx.x;
    if (i < n8) {
        const float4 a = ((const float4*)src)[2 * i];
        const float4 b = ((const float4*)src)[2 * i + 1];
        uint4 o;
        half2 h;
        h = __floats2half2_rn(a.x, a.y); o.x = *(uint32_t*)&h;
        h = __floats2half2_rn(a.z, a.w); o.y = *(uint32_t*)&h;
        h = __floats2half2_rn(b.x, b.y); o.z = *(uint32_t*)&h;
        h = __floats2half2_rn(b.z, b.w); o.w = *(uint32_t*)&h;
        ((uint4*)dst)[i] = o;
    }
}

// fp32 -> tf32(rna) copy
__global__ __launch_bounds__(256)
void f32_to_tf32(const float* __restrict__ src, float* __restrict__ dst, int n4)
{
    int i = blockIdx.x * 256 + threadIdx.x;
    if (i < n4) {
        float4 v = ((const float4*)src)[i];
        v.x = f2tf(v.x); v.y = f2tf(v.y); v.z = f2tf(v.z); v.w = f2tf(v.w);
        ((float4*)dst)[i] = v;
    }
}

// softmax over rows of 2048 halfs; 256 threads, one uint4 (8 halfs) per thread
__global__ __launch_bounds__(256)
void softmax_h(__half* __restrict__ S)
{
    uint4* p = (uint4*)(S + (long long)blockIdx.x * SKVdim);
    const int tid = threadIdx.x, wid = tid >> 5, lane = tid & 31;
    __shared__ float red[8];

    uint4 v = p[tid];
    float f[8];
    { float2 t;
      t = __half22float2(*(half2*)&v.x); f[0]=t.x; f[1]=t.y;
      t = __half22float2(*(half2*)&v.y); f[2]=t.x; f[3]=t.y;
      t = __half22float2(*(half2*)&v.z); f[4]=t.x; f[5]=t.y;
      t = __half22float2(*(half2*)&v.w); f[6]=t.x; f[7]=t.y; }

    float m = f[0];
    #pragma unroll
    for (int j = 1; j < 8; j++) m = fmaxf(m, f[j]);
    #pragma unroll
    for (int o = 16; o > 0; o >>= 1) m = fmaxf(m, __shfl_xor_sync(~0u, m, o));
    if (lane == 0) red[wid] = m;
    __syncthreads();
    m = red[0];
    #pragma unroll
    for (int w = 1; w < 8; w++) m = fmaxf(m, red[w]);
    __syncthreads();

    float s = 0.f;
    #pragma unroll
    for (int j = 0; j < 8; j++) { f[j] = __expf(f[j] - m); s += f[j]; }
    #pragma unroll
    for (int o = 16; o > 0; o >>= 1) s += __shfl_xor_sync(~0u, s, o);
    if (lane == 0) red[wid] = s;
    __syncthreads();
    s = red[0] + red[1] + red[2] + red[3] + red[4] + red[5] + red[6] + red[7];

    const float inv = 1.0f / s;
    half2 h;
    h = __floats2half2_rn(f[0]*inv, f[1]*inv); v.x = *(uint32_t*)&h;
    h = __floats2half2_rn(f[2]*inv, f[3]*inv); v.y = *(uint32_t*)&h;
    h = __floats2half2_rn(f[4]*inv, f[5]*inv); v.z = *(uint32_t*)&h;
    h = __floats2half2_rn(f[6]*inv, f[7]*inv); v.w = *(uint32_t*)&h;
    p[tid] = v;
}

extern "C" void kernel_launch(void* const* d_in, const int* in_sizes, int n_in,
                              void* d_out, int out_size)
{
    const float* x  = (const float*)d_in[0];
    const float* ce = (const float*)d_in[1];
    const float* Wq = (const float*)d_in[2];
    const float* bq = (const float*)d_in[3];
    const float* Wk = (const float*)d_in[4];
    const float* bk = (const float*)d_in[5];
    const float* Wv = (const float*)d_in[6];
    const float* bv = (const float*)d_in[7];
    const float* Wo = (const float*)d_in[8];
    const float* bo = (const float*)d_in[9];
    float* out = (float*)d_out;

    __half *xh, *ceh, *Wqh, *Wkh, *Wvh, *Qh, *Kh, *Vth, *Sh;
    float *Wot, *At;
    cudaGetSymbolAddress((void**)&xh,  g_xh);
    cudaGetSymbolAddress((void**)&ceh, g_ceh);
    cudaGetSymbolAddress((void**)&Wqh, g_Wqh);
    cudaGetSymbolAddress((void**)&Wkh, g_Wkh);
    cudaGetSymbolAddress((void**)&Wvh, g_Wvh);
    cudaGetSymbolAddress((void**)&Wot, g_Wot);
    cudaGetSymbolAddress((void**)&Qh,  g_Qh);
    cudaGetSymbolAddress((void**)&Kh,  g_Kh);
    cudaGetSymbolAddress((void**)&Vth, g_Vth);
    cudaGetSymbolAddress((void**)&Sh,  g_Sh);
    cudaGetSymbolAddress((void**)&At,  g_At);

    #define SETSM(KF) cudaFuncSetAttribute(KF, cudaFuncAttributeMaxDynamicSharedMemorySize, SMEM_BYTES)
    SETSM((gemm_k<true , true , true , false, false, false>));   // Q, K proj
    SETSM((gemm_k<true , true , false, true , false, false>));   // Vt
    SETSM((gemm_k<true , true , false, false, false, false>));   // scores
    SETSM((gemm_k<true , false, false, false, true , true >));   // At
    SETSM((gemm_k<false, false, true , false, false, false>));   // final tf32

    dim3 blk(128);

    // 0: dtype conversions
    const int act8 = Mtot * Cdim / 8;     // 1048576
    const int w8   = Cdim * Cdim / 8;     // 131072
    f32_to_f16<<<act8 / 256, 256>>>(x,  xh,  act8);
    f32_to_f16<<<act8 / 256, 256>>>(ce, ceh, act8);
    f32_to_f16<<<w8 / 256, 256>>>(Wq, Wqh, w8);
    f32_to_f16<<<w8 / 256, 256>>>(Wk, Wkh, w8);
    f32_to_f16<<<w8 / 256, 256>>>(Wv, Wvh, w8);
    f32_to_tf32<<<Cdim * Cdim / 4 / 256, 256>>>(Wo, Wot, Cdim * Cdim / 4);

    // Qh = xh @ Wqh^T + bq
    gemm_k<true,true,true,false,false,false><<<dim3(Cdim/128, Mtot/128, 1), blk, SMEM_BYTES>>>(
        xh, Wqh, bq, nullptr, Qh, Cdim, Cdim, Cdim, Cdim/64, 0,0,0,0, 1.0f);
    // Kh = ceh @ Wkh^T + bk
    gemm_k<true,true,true,false,false,false><<<dim3(Cdim/128, Mtot/128, 1), blk, SMEM_BYTES>>>(
        ceh, Wkh, bk, nullptr, Kh, Cdim, Cdim, Cdim, Cdim/64, 0,0,0,0, 1.0f);
    // Vth = Wvh @ ceh^T + bv   -> [C, B*SKV], bias over rows (channels)
    gemm_k<true,true,false,true,false,false><<<dim3(Mtot/128, Cdim/128, 1), blk, SMEM_BYTES>>>(
        Wvh, ceh, bv, nullptr, Vth, Cdim, Cdim, Mtot, Cdim/64, 0,0,0,0, 1.0f);
    // Sh = (Qh @ Kh^T) / 32   (batched)
    gemm_k<true,true,false,false,false,false><<<dim3(SKVdim/128, SQdim/128, Bdim), blk, SMEM_BYTES>>>(
        Qh, Kh, nullptr, nullptr, Sh, Cdim, Cdim, SKVdim, Cdim/64,
        (long long)SQdim*Cdim, (long long)SKVdim*Cdim, (long long)SQdim*SKVdim, 0, 0.03125f);
    // Ph = softmax(Sh)
    softmax_h<<<Bdim * SQdim, 256>>>(Sh);
    // At = Ph @ Vth^T + x    (float out, tf32-rounded; Vth column block per batch)
    gemm_k<true,false,false,false,true,true><<<dim3(Cdim/128, SQdim/128, Bdim), blk, SMEM_BYTES>>>(
        Sh, Vth, nullptr, x, At, SKVdim, Mtot, Cdim, SKVdim/64,
        (long long)SQdim*SKVdim, (long long)SKVdim, (long long)SQdim*Cdim,
        (long long)SQdim*Cdim, 1.0f);
    // out = At @ Wot^T + bo  (tf32)
    gemm_k<false,false,true,false,false,false><<<dim3(Cdim/128, Mtot/128, 1), blk, SMEM_BYTES>>>(
        At, Wot, bo, nullptr, out, Cdim, Cdim, Cdim, Cdim/32, 0,0,0,0, 1.0f);
}

// round 6
// speedup vs baseline: 2.5978x; 1.8040x over previous
#include <cuda_runtime.h>
#include <cuda_fp16.h>
#include <cstdint>

// ---------------------------------------------------------------------------
// SpatialTransformer R6: fp16 mma.sync attention path + tf32 output proj,
// R3's occupancy shape (256 thr, 8 warps 64x32, 2 CTAs/SM) + fp16 density.
//   xh,ceh,Wqh,Wkh,Wvh = fp16(inputs);  Wot = tf32(Wo)
//   Qh  = xh @ Wqh^T + bq            fp16, half out, bias-N
//   Kh  = ceh@ Wkh^T + bk            fp16, half out, bias-N
//   Vth = Wvh@ ceh^T + bv            fp16, half out, bias-M -> [C, B*SKV]
//   Sh  = (Qh @ Kh^T)/32             fp16, half out, batched
//   Ph  = softmax_rows(Sh)           half in/out
//   At  = Ph @ Vth^T + x             fp16, float out (rna), +Add
//   out = At @ Wot^T + bo            tf32, float out
// ---------------------------------------------------------------------------

#define Cdim  1024
#define Bdim  4
#define SQdim 2048
#define SKVdim 2048
#define Mtot  (Bdim * SQdim)            // 8192

__device__ __half g_xh [(long long)Mtot * Cdim];
__device__ __half g_ceh[(long long)Mtot * Cdim];
__device__ __half g_Wqh[(long long)Cdim * Cdim];
__device__ __half g_Wkh[(long long)Cdim * Cdim];
__device__ __half g_Wvh[(long long)Cdim * Cdim];
__device__ float  g_Wot[(long long)Cdim * Cdim];
__device__ __half g_Qh [(long long)Mtot * Cdim];
__device__ __half g_Kh [(long long)Mtot * Cdim];
__device__ __half g_Vth[(long long)Cdim * Mtot];
__device__ __half g_Sh [(long long)Bdim * SQdim * SKVdim];
__device__ float  g_At [(long long)Mtot * Cdim];

__device__ __forceinline__ float f2tf(float f){
    uint32_t r; asm("cvt.rna.tf32.f32 %0, %1;" : "=r"(r) : "f"(f));
    return __uint_as_float(r);
}

__device__ __forceinline__ void mma_f16(float* d, const uint32_t* a, const uint32_t* b){
    asm volatile("mma.sync.aligned.m16n8k16.row.col.f32.f16.f16.f32 "
        "{%0,%1,%2,%3}, {%4,%5,%6,%7}, {%8,%9}, {%0,%1,%2,%3};"
        : "+f"(d[0]), "+f"(d[1]), "+f"(d[2]), "+f"(d[3])
        : "r"(a[0]), "r"(a[1]), "r"(a[2]), "r"(a[3]), "r"(b[0]), "r"(b[1]));
}
__device__ __forceinline__ void mma_tf(float* d, const uint32_t* a, const uint32_t* b){
    asm volatile("mma.sync.aligned.m16n8k8.row.col.f32.tf32.tf32.f32 "
        "{%0,%1,%2,%3}, {%4,%5,%6,%7}, {%8,%9}, {%0,%1,%2,%3};"
        : "+f"(d[0]), "+f"(d[1]), "+f"(d[2]), "+f"(d[3])
        : "r"(a[0]), "r"(a[1]), "r"(a[2]), "r"(a[3]), "r"(b[0]), "r"(b[1]));
}

#define LDM4(r0,r1,r2,r3,addr) \
  asm volatile("ldmatrix.sync.aligned.m8n8.x4.shared.b16 {%0,%1,%2,%3}, [%4];" \
    : "=r"(r0),"=r"(r1),"=r"(r2),"=r"(r3) : "r"(addr))

#define CPA16(dst, src) \
  asm volatile("cp.async.cg.shared.global [%0], [%1], 16;" :: "r"(dst), "l"(src))
#define CPA_COMMIT() asm volatile("cp.async.commit_group;" ::: "memory")
#define CPA_WAIT1()  asm volatile("cp.async.wait_group 1;" ::: "memory")
#define CPA_WAIT0()  asm volatile("cp.async.wait_group 0;" ::: "memory")

// Tile: 128 rows x (128B data + 16B pad) = 18432 B
#define RSTR 144
#define TILEB 18432
#define BUFB  36864
#define SMEM_BYTES 73728

// D[128x128] tile of scale*(A @ B^T) [+biasN|+biasM] [+Add] [rna]
// F16: half elements, BK=64; else float (tf32 bits), BK=32.
// A: [*,K] row-major lda; B: [*,K] row-major ldb. K%BK==0.
template<bool F16, bool HOUT, bool BN_, bool BM_, bool ADD_, bool RND_>
__global__ __launch_bounds__(256, 2)
void gemm_k(const void* __restrict__ A_, const void* __restrict__ B_,
            const float* __restrict__ bias, const float* __restrict__ Add,
            void* __restrict__ C_,
            int lda, int ldb, int ldc, int NK,
            long long sA, long long sB, long long sC, long long sAdd,
            float scale)
{
    using TI = typename std::conditional<F16, __half, float>::type;
    const int EPC = F16 ? 8 : 4;      // elements per 16B chunk
    const int BKE = F16 ? 64 : 32;    // elements per k-tile

    extern __shared__ char smem[];
    uint32_t sbase;
    asm("{ .reg .u64 t; cvta.to.shared.u64 t, %1; cvt.u32.u64 %0, t; }"
        : "=r"(sbase) : "l"(smem));

    const int tid = threadIdx.x, wid = tid >> 5, lane = tid & 31;

    const TI* A = (const TI*)A_ + (long long)blockIdx.z * sA;
    const TI* B = (const TI*)B_ + (long long)blockIdx.z * sB;
    if (ADD_) Add += (long long)blockIdx.z * sAdd;

    const int m0 = blockIdx.y * 128;
    const int n0 = blockIdx.x * 128;

    // ---- cp.async loader: 2 threads per row, 4x16B chunks each ----
    const int lrow = tid >> 1;
    const int lhalf = tid & 1;
    const TI* ap = A + (long long)(m0 + lrow) * lda + lhalf * 4 * EPC;
    const TI* bp = B + (long long)(n0 + lrow) * ldb + lhalf * 4 * EPC;
    const uint32_t aSt = sbase + lrow * RSTR + lhalf * 64;
    const uint32_t bSt = sbase + TILEB + lrow * RSTR + lhalf * 64;

    // ---- warp mapping: 8 warps, 64x32 each ----
    const int wm = (wid & 1) * 64;
    const int wn = (wid >> 1) * 32;
    const int qr = lane >> 2, qc = lane & 3;
    uint32_t aF[4], bF[2];
    #pragma unroll
    for (int mi = 0; mi < 4; mi++)
        aF[mi] = sbase + (wm + mi * 16 + (lane & 15)) * RSTR + (lane >> 4) * 16;
    #pragma unroll
    for (int nt = 0; nt < 2; nt++)
        bF[nt] = sbase + TILEB +
                 (wn + nt * 16 + (lane & 7) + ((lane >> 4) << 3)) * RSTR +
                 ((lane >> 3) & 1) * 16;

    float acc[4][4][4];
    #pragma unroll
    for (int mi = 0; mi < 4; mi++)
        #pragma unroll
        for (int nj = 0; nj < 4; nj++)
            #pragma unroll
            for (int j = 0; j < 4; j++) acc[mi][nj][j] = 0.f;

    // ---- prologue: k-tile 0 -> buffer 0 ----
    #pragma unroll
    for (int i = 0; i < 4; i++) CPA16(aSt + i * 16, ap + i * EPC);
    #pragma unroll
    for (int i = 0; i < 4; i++) CPA16(bSt + i * 16, bp + i * EPC);
    CPA_COMMIT();

    for (int k = 0; k < NK; k++) {
        const int buf = k & 1;
        if (k + 1 < NK) {
            const uint32_t nb = (buf ^ 1) * BUFB;
            const int k0 = (k + 1) * BKE;
            #pragma unroll
            for (int i = 0; i < 4; i++) CPA16(aSt + nb + i * 16, ap + k0 + i * EPC);
            #pragma unroll
            for (int i = 0; i < 4; i++) CPA16(bSt + nb + i * 16, bp + k0 + i * EPC);
            CPA_COMMIT();
            CPA_WAIT1();
        } else {
            CPA_WAIT0();
        }
        __syncthreads();

        const uint32_t bo = buf * BUFB;
        #pragma unroll
        for (int s = 0; s < 4; s++) {
            uint32_t afr[4][4];
            #pragma unroll
            for (int mi = 0; mi < 4; mi++)
                LDM4(afr[mi][0], afr[mi][1], afr[mi][2], afr[mi][3],
                     aF[mi] + bo + s * 32);
            uint32_t bfr[4][2];
            #pragma unroll
            for (int nt = 0; nt < 2; nt++) {
                uint32_t t0, t1, t2, t3;
                LDM4(t0, t1, t2, t3, bF[nt] + bo + s * 32);
                bfr[nt * 2][0] = t0;     bfr[nt * 2][1] = t1;
                bfr[nt * 2 + 1][0] = t2; bfr[nt * 2 + 1][1] = t3;
            }
            #pragma unroll
            for (int mi = 0; mi < 4; mi++)
                #pragma unroll
                for (int nj = 0; nj < 4; nj++) {
                    if (F16) mma_f16(acc[mi][nj], afr[mi], bfr[nj]);
                    else     mma_tf (acc[mi][nj], afr[mi], bfr[nj]);
                }
        }
        __syncthreads();
    }

    // ---- epilogue: direct stores, fused scale/bias/residual/rounding ----
    #pragma unroll
    for (int mi = 0; mi < 4; mi++) {
        #pragma unroll
        for (int h = 0; h < 2; h++) {
            const long long gm = m0 + wm + mi * 16 + qr + h * 8;
            float bm = 0.f;
            if (BM_) bm = bias[gm];
            #pragma unroll
            for (int nj = 0; nj < 4; nj++) {
                const int gn = n0 + wn + nj * 8 + qc * 2;
                float vx = acc[mi][nj][h * 2 + 0] * scale;
                float vy = acc[mi][nj][h * 2 + 1] * scale;
                if (BN_) { const float2 bb = *(const float2*)(bias + gn); vx += bb.x; vy += bb.y; }
                if (BM_) { vx += bm; vy += bm; }
                if (ADD_) {
                    const float2 ad = *(const float2*)(Add + gm * ldc + gn);
                    vx += ad.x; vy += ad.y;
                }
                if (HOUT) {
                    *(half2*)((__half*)C_ + (long long)blockIdx.z * sC + gm * ldc + gn) =
                        __floats2half2_rn(vx, vy);
                } else {
                    if (RND_) { vx = f2tf(vx); vy = f2tf(vy); }
                    *(float2*)((float*)C_ + (long long)blockIdx.z * sC + gm * ldc + gn) =
                        make_float2(vx, vy);
                }
            }
        }
    }
}

// fp32 -> fp16, 8 elems/thread
__global__ __launch_bounds__(256)
void f32_to_f16(const float* __restrict__ src, __half* __restrict__ dst, int n8)
{
    int i = blockIdx.x * 256 + threadIdx.x;
    if (i < n8) {
        const float4 a = ((const float4*)src)[2 * i];
        const float4 b = ((const float4*)src)[2 * i + 1];
        uint4 o;
        half2 h;
        h = __floats2half2_rn(a.x, a.y); o.x = *(uint32_t*)&h;
        h = __floats2half2_rn(a.z, a.w); o.y = *(uint32_t*)&h;
        h = __floats2half2_rn(b.x, b.y); o.z = *(uint32_t*)&h;
        h = __floats2half2_rn(b.z, b.w); o.w = *(uint32_t*)&h;
        ((uint4*)dst)[i] = o;
    }
}

// fp32 -> tf32(rna)
__global__ __launch_bounds__(256)
void f32_to_tf32(const float* __restrict__ src, float* __restrict__ dst, int n4)
{
    int i = blockIdx.x * 256 + threadIdx.x;
    if (i < n4) {
        float4 v = ((const float4*)src)[i];
        v.x = f2tf(v.x); v.y = f2tf(v.y); v.z = f2tf(v.z); v.w = f2tf(v.w);
        ((float4*)dst)[i] = v;
    }
}

// softmax over rows of 2048 halfs; 256 threads, 8 halfs/thread
__global__ __launch_bounds__(256)
void softmax_h(__half* __restrict__ S)
{
    uint4* p = (uint4*)(S + (long long)blockIdx.x * SKVdim);
    const int tid = threadIdx.x, wid = tid >> 5, lane = tid & 31;
    __shared__ float red[8];

    uint4 v = p[tid];
    float f[8];
    { float2 t;
      t = __half22float2(*(half2*)&v.x); f[0]=t.x; f[1]=t.y;
      t = __half22float2(*(half2*)&v.y); f[2]=t.x; f[3]=t.y;
      t = __half22float2(*(half2*)&v.z); f[4]=t.x; f[5]=t.y;
      t = __half22float2(*(half2*)&v.w); f[6]=t.x; f[7]=t.y; }

    float m = f[0];
    #pragma unroll
    for (int j = 1; j < 8; j++) m = fmaxf(m, f[j]);
    #pragma unroll
    for (int o = 16; o > 0; o >>= 1) m = fmaxf(m, __shfl_xor_sync(~0u, m, o));
    if (lane == 0) red[wid] = m;
    __syncthreads();
    m = red[0];
    #pragma unroll
    for (int w = 1; w < 8; w++) m = fmaxf(m, red[w]);
    __syncthreads();

    float s = 0.f;
    #pragma unroll
    for (int j = 0; j < 8; j++) { f[j] = __expf(f[j] - m); s += f[j]; }
    #pragma unroll
    for (int o = 16; o > 0; o >>= 1) s += __shfl_xor_sync(~0u, s, o);
    if (lane == 0) red[wid] = s;
    __syncthreads();
    s = red[0] + red[1] + red[2] + red[3] + red[4] + red[5] + red[6] + red[7];

    const float inv = 1.0f / s;
    half2 h;
    h = __floats2half2_rn(f[0]*inv, f[1]*inv); v.x = *(uint32_t*)&h;
    h = __floats2half2_rn(f[2]*inv, f[3]*inv); v.y = *(uint32_t*)&h;
    h = __floats2half2_rn(f[4]*inv, f[5]*inv); v.z = *(uint32_t*)&h;
    h = __floats2half2_rn(f[6]*inv, f[7]*inv); v.w = *(uint32_t*)&h;
    p[tid] = v;
}

extern "C" void kernel_launch(void* const* d_in, const int* in_sizes, int n_in,
                              void* d_out, int out_size)
{
    const float* x  = (const float*)d_in[0];
    const float* ce = (const float*)d_in[1];
    const float* Wq = (const float*)d_in[2];
    const float* bq = (const float*)d_in[3];
    const float* Wk = (const float*)d_in[4];
    const float* bk = (const float*)d_in[5];
    const float* Wv = (const float*)d_in[6];
    const float* bv = (const float*)d_in[7];
    const float* Wo = (const float*)d_in[8];
    const float* bo = (const float*)d_in[9];
    float* out = (float*)d_out;

    __half *xh, *ceh, *Wqh, *Wkh, *Wvh, *Qh, *Kh, *Vth, *Sh;
    float *Wot, *At;
    cudaGetSymbolAddress((void**)&xh,  g_xh);
    cudaGetSymbolAddress((void**)&ceh, g_ceh);
    cudaGetSymbolAddress((void**)&Wqh, g_Wqh);
    cudaGetSymbolAddress((void**)&Wkh, g_Wkh);
    cudaGetSymbolAddress((void**)&Wvh, g_Wvh);
    cudaGetSymbolAddress((void**)&Wot, g_Wot);
    cudaGetSymbolAddress((void**)&Qh,  g_Qh);
    cudaGetSymbolAddress((void**)&Kh,  g_Kh);
    cudaGetSymbolAddress((void**)&Vth, g_Vth);
    cudaGetSymbolAddress((void**)&Sh,  g_Sh);
    cudaGetSymbolAddress((void**)&At,  g_At);

    #define SETSM(KF) cudaFuncSetAttribute(KF, cudaFuncAttributeMaxDynamicSharedMemorySize, SMEM_BYTES)
    SETSM((gemm_k<true , true , true , false, false, false>));
    SETSM((gemm_k<true , true , false, true , false, false>));
    SETSM((gemm_k<true , true , false, false, false, false>));
    SETSM((gemm_k<true , false, false, false, true , true >));
    SETSM((gemm_k<false, false, true , false, false, false>));

    dim3 blk(256);

    const int act8 = Mtot * Cdim / 8;
    const int w8   = Cdim * Cdim / 8;
    f32_to_f16<<<act8 / 256, 256>>>(x,  xh,  act8);
    f32_to_f16<<<act8 / 256, 256>>>(ce, ceh, act8);
    f32_to_f16<<<w8 / 256, 256>>>(Wq, Wqh, w8);
    f32_to_f16<<<w8 / 256, 256>>>(Wk, Wkh, w8);
    f32_to_f16<<<w8 / 256, 256>>>(Wv, Wvh, w8);
    f32_to_tf32<<<Cdim * Cdim / 4 / 256, 256>>>(Wo, Wot, Cdim * Cdim / 4);

    // Qh = xh @ Wqh^T + bq
    gemm_k<true,true,true,false,false,false><<<dim3(Cdim/128, Mtot/128, 1), blk, SMEM_BYTES>>>(
        xh, Wqh, bq, nullptr, Qh, Cdim, Cdim, Cdim, Cdim/64, 0,0,0,0, 1.0f);
    // Kh = ceh @ Wkh^T + bk
    gemm_k<true,true,true,false,false,false><<<dim3(Cdim/128, Mtot/128, 1), blk, SMEM_BYTES>>>(
        ceh, Wkh, bk, nullptr, Kh, Cdim, Cdim, Cdim, Cdim/64, 0,0,0,0, 1.0f);
    // Vth = Wvh @ ceh^T + bv   -> [C, B*SKV]
    gemm_k<true,true,false,true,false,false><<<dim3(Mtot/128, Cdim/128, 1), blk, SMEM_BYTES>>>(
        Wvh, ceh, bv, nullptr, Vth, Cdim, Cdim, Mtot, Cdim/64, 0,0,0,0, 1.0f);
    // Sh = (Qh @ Kh^T) / 32
    gemm_k<true,true,false,false,false,false><<<dim3(SKVdim/128, SQdim/128, Bdim), blk, SMEM_BYTES>>>(
        Qh, Kh, nullptr, nullptr, Sh, Cdim, Cdim, SKVdim, Cdim/64,
        (long long)SQdim*Cdim, (long long)SKVdim*Cdim, (long long)SQdim*SKVdim, 0, 0.03125f);
    // Ph = softmax(Sh)
    softmax_h<<<Bdim * SQdim, 256>>>(Sh);
    // At = Ph @ Vth^T + x
    gemm_k<true,false,false,false,true,true><<<dim3(Cdim/128, SQdim/128, Bdim), blk, SMEM_BYTES>>>(
        Sh, Vth, nullptr, x, At, SKVdim, Mtot, Cdim, SKVdim/64,
        (long long)SQdim*SKVdim, (long long)SKVdim, (long long)SQdim*Cdim,
        (long long)SQdim*Cdim, 1.0f);
    // out = At @ Wot^T + bo (tf32)
    gemm_k<false,false,true,false,false,false><<<dim3(Cdim/128, Mtot/128, 1), blk, SMEM_BYTES>>>(
        At, Wot, bo, nullptr, out, Cdim, Cdim, Cdim, Cdim/32, 0,0,0,0, 1.0f);
}

// round 7
// speedup vs baseline: 2.9104x; 1.1203x over previous
#include <cuda_runtime.h>
#include <cuda_fp16.h>
#include <cstdint>

// ---------------------------------------------------------------------------
// SpatialTransformer R7: R6 (fp16 mma attention + tf32 out-proj, 8x64x32 warps,
// 2 CTAs/SM) + 3-stage cp.async pipeline + merged Q/K projection launch.
// ---------------------------------------------------------------------------

#define Cdim  1024
#define Bdim  4
#define SQdim 2048
#define SKVdim 2048
#define Mtot  (Bdim * SQdim)            // 8192

__device__ __half g_xh [(long long)Mtot * Cdim];
__device__ __half g_ceh[(long long)Mtot * Cdim];
__device__ __half g_Wqh[(long long)Cdim * Cdim];
__device__ __half g_Wkh[(long long)Cdim * Cdim];
__device__ __half g_Wvh[(long long)Cdim * Cdim];
__device__ float  g_Wot[(long long)Cdim * Cdim];
__device__ __half g_Qh [(long long)Mtot * Cdim];
__device__ __half g_Kh [(long long)Mtot * Cdim];
__device__ __half g_Vth[(long long)Cdim * Mtot];
__device__ __half g_Sh [(long long)Bdim * SQdim * SKVdim];
__device__ float  g_At [(long long)Mtot * Cdim];

__device__ __forceinline__ float f2tf(float f){
    uint32_t r; asm("cvt.rna.tf32.f32 %0, %1;" : "=r"(r) : "f"(f));
    return __uint_as_float(r);
}

__device__ __forceinline__ void mma_f16(float* d, const uint32_t* a, const uint32_t* b){
    asm volatile("mma.sync.aligned.m16n8k16.row.col.f32.f16.f16.f32 "
        "{%0,%1,%2,%3}, {%4,%5,%6,%7}, {%8,%9}, {%0,%1,%2,%3};"
        : "+f"(d[0]), "+f"(d[1]), "+f"(d[2]), "+f"(d[3])
        : "r"(a[0]), "r"(a[1]), "r"(a[2]), "r"(a[3]), "r"(b[0]), "r"(b[1]));
}
__device__ __forceinline__ void mma_tf(float* d, const uint32_t* a, const uint32_t* b){
    asm volatile("mma.sync.aligned.m16n8k8.row.col.f32.tf32.tf32.f32 "
        "{%0,%1,%2,%3}, {%4,%5,%6,%7}, {%8,%9}, {%0,%1,%2,%3};"
        : "+f"(d[0]), "+f"(d[1]), "+f"(d[2]), "+f"(d[3])
        : "r"(a[0]), "r"(a[1]), "r"(a[2]), "r"(a[3]), "r"(b[0]), "r"(b[1]));
}

#define LDM4(r0,r1,r2,r3,addr) \
  asm volatile("ldmatrix.sync.aligned.m8n8.x4.shared.b16 {%0,%1,%2,%3}, [%4];" \
    : "=r"(r0),"=r"(r1),"=r"(r2),"=r"(r3) : "r"(addr))

#define CPA16(dst, src) \
  asm volatile("cp.async.cg.shared.global [%0], [%1], 16;" :: "r"(dst), "l"(src))
#define CPA_COMMIT() asm volatile("cp.async.commit_group;" ::: "memory")
#define CPA_WAIT1()  asm volatile("cp.async.wait_group 1;" ::: "memory")
#define CPA_WAIT0()  asm volatile("cp.async.wait_group 0;" ::: "memory")

// Tile: 128 rows x (128B data + 16B pad) = 18432 B; A+B per stage = 36864 B
#define RSTR 144
#define TILEB 18432
#define BUFB  36864
#define NSTAGE 3
#define SMEM_BYTES (BUFB * NSTAGE)     // 110592

// D[128x128] tile of scale*(A @ B^T) [+biasN|+biasM] [+Add] [rna]
// F16: half elements, BK=64; else float (tf32 bits), BK=32.
// MG2: blockIdx.z in {0,1} selects (A,B,bias,C) vs (A2,B2,bias2,C2), no batch.
template<bool F16, bool HOUT, bool BN_, bool BM_, bool ADD_, bool RND_, bool MG2>
__global__ __launch_bounds__(256, 2)
void gemm_k(const void* __restrict__ A_, const void* __restrict__ B_,
            const float* __restrict__ bias, const float* __restrict__ Add,
            void* __restrict__ C_,
            const void* __restrict__ A2_, const void* __restrict__ B2_,
            const float* __restrict__ bias2, void* __restrict__ C2_,
            int lda, int ldb, int ldc, int NK,
            long long sA, long long sB, long long sC, long long sAdd,
            float scale)
{
    using TI = typename std::conditional<F16, __half, float>::type;
    const int EPC = F16 ? 8 : 4;      // elements per 16B chunk
    const int BKE = F16 ? 64 : 32;    // elements per k-tile

    extern __shared__ char smem[];
    uint32_t sbase;
    asm("{ .reg .u64 t; cvta.to.shared.u64 t, %1; cvt.u32.u64 %0, t; }"
        : "=r"(sbase) : "l"(smem));

    const int tid = threadIdx.x, wid = tid >> 5, lane = tid & 31;

    const TI* A;
    const TI* B;
    void* Csel;
    if (MG2) {
        const bool s1 = (blockIdx.z != 0);
        A    = (const TI*)(s1 ? A2_ : A_);
        B    = (const TI*)(s1 ? B2_ : B_);
        bias = s1 ? bias2 : bias;
        Csel = s1 ? C2_ : C_;
    } else {
        A = (const TI*)A_ + (long long)blockIdx.z * sA;
        B = (const TI*)B_ + (long long)blockIdx.z * sB;
        Csel = C_;
        if (ADD_) Add += (long long)blockIdx.z * sAdd;
    }

    const int m0 = blockIdx.y * 128;
    const int n0 = blockIdx.x * 128;

    // ---- cp.async loader: 2 threads per row, 4x16B chunks each ----
    const int lrow = tid >> 1;
    const int lhalf = tid & 1;
    const TI* ap = A + (long long)(m0 + lrow) * lda + lhalf * 4 * EPC;
    const TI* bp = B + (long long)(n0 + lrow) * ldb + lhalf * 4 * EPC;
    const uint32_t aSt = sbase + lrow * RSTR + lhalf * 64;
    const uint32_t bSt = sbase + TILEB + lrow * RSTR + lhalf * 64;

    // ---- warp mapping: 8 warps, 64x32 each ----
    const int wm = (wid & 1) * 64;
    const int wn = (wid >> 1) * 32;
    const int qr = lane >> 2, qc = lane & 3;
    uint32_t aF[4], bF[2];
    #pragma unroll
    for (int mi = 0; mi < 4; mi++)
        aF[mi] = sbase + (wm + mi * 16 + (lane & 15)) * RSTR + (lane >> 4) * 16;
    #pragma unroll
    for (int nt = 0; nt < 2; nt++)
        bF[nt] = sbase + TILEB +
                 (wn + nt * 16 + (lane & 7) + ((lane >> 4) << 3)) * RSTR +
                 ((lane >> 3) & 1) * 16;

    float acc[4][4][4];
    #pragma unroll
    for (int mi = 0; mi < 4; mi++)
        #pragma unroll
        for (int nj = 0; nj < 4; nj++)
            #pragma unroll
            for (int j = 0; j < 4; j++) acc[mi][nj][j] = 0.f;

    // ---- prologue: tiles 0,1 -> stages 0,1 ----
    #pragma unroll
    for (int i = 0; i < 4; i++) CPA16(aSt + i * 16, ap + i * EPC);
    #pragma unroll
    for (int i = 0; i < 4; i++) CPA16(bSt + i * 16, bp + i * EPC);
    CPA_COMMIT();
    if (NK > 1) {
        #pragma unroll
        for (int i = 0; i < 4; i++) CPA16(aSt + BUFB + i * 16, ap + BKE + i * EPC);
        #pragma unroll
        for (int i = 0; i < 4; i++) CPA16(bSt + BUFB + i * 16, bp + BKE + i * EPC);
        CPA_COMMIT();
    }

    uint32_t bo_cur = 0;                       // stage of tile k
    uint32_t bo_pre = 2 * BUFB;                // stage of tile k+2
    for (int k = 0; k < NK; k++) {
        if (k + 1 < NK) CPA_WAIT1(); else CPA_WAIT0();
        __syncthreads();                       // everyone done with stage bo_pre
        if (k + 2 < NK) {
            const int k0 = (k + 2) * BKE;
            #pragma unroll
            for (int i = 0; i < 4; i++) CPA16(aSt + bo_pre + i * 16, ap + k0 + i * EPC);
            #pragma unroll
            for (int i = 0; i < 4; i++) CPA16(bSt + bo_pre + i * 16, bp + k0 + i * EPC);
            CPA_COMMIT();
        }

        const uint32_t bo = bo_cur;
        #pragma unroll
        for (int s = 0; s < 4; s++) {
            uint32_t afr[4][4];
            #pragma unroll
            for (int mi = 0; mi < 4; mi++)
                LDM4(afr[mi][0], afr[mi][1], afr[mi][2], afr[mi][3],
                     aF[mi] + bo + s * 32);
            uint32_t bfr[4][2];
            #pragma unroll
            for (int nt = 0; nt < 2; nt++) {
                uint32_t t0, t1, t2, t3;
                LDM4(t0, t1, t2, t3, bF[nt] + bo + s * 32);
                bfr[nt * 2][0] = t0;     bfr[nt * 2][1] = t1;
                bfr[nt * 2 + 1][0] = t2; bfr[nt * 2 + 1][1] = t3;
            }
            #pragma unroll
            for (int mi = 0; mi < 4; mi++)
                #pragma unroll
                for (int nj = 0; nj < 4; nj++) {
                    if (F16) mma_f16(acc[mi][nj], afr[mi], bfr[nj]);
                    else     mma_tf (acc[mi][nj], afr[mi], bfr[nj]);
                }
        }
        bo_pre = bo_cur;
        bo_cur = (bo_cur == 2 * BUFB) ? 0 : bo_cur + BUFB;
    }

    // ---- epilogue: direct stores, fused scale/bias/residual/rounding ----
    #pragma unroll
    for (int mi = 0; mi < 4; mi++) {
        #pragma unroll
        for (int h = 0; h < 2; h++) {
            const long long gm = m0 + wm + mi * 16 + qr + h * 8;
            float bm = 0.f;
            if (BM_) bm = bias[gm];
            #pragma unroll
            for (int nj = 0; nj < 4; nj++) {
                const int gn = n0 + wn + nj * 8 + qc * 2;
                float vx = acc[mi][nj][h * 2 + 0] * scale;
                float vy = acc[mi][nj][h * 2 + 1] * scale;
                if (BN_) { const float2 bb = *(const float2*)(bias + gn); vx += bb.x; vy += bb.y; }
                if (BM_) { vx += bm; vy += bm; }
                if (ADD_) {
                    const float2 ad = *(const float2*)(Add + gm * ldc + gn);
                    vx += ad.x; vy += ad.y;
                }
                if (HOUT) {
                    __half* Co = (__half*)Csel + (MG2 ? 0ll : (long long)blockIdx.z * sC);
                    *(half2*)(Co + gm * ldc + gn) = __floats2half2_rn(vx, vy);
                } else {
                    if (RND_) { vx = f2tf(vx); vy = f2tf(vy); }
                    float* Co = (float*)Csel + (MG2 ? 0ll : (long long)blockIdx.z * sC);
                    *(float2*)(Co + gm * ldc + gn) = make_float2(vx, vy);
                }
            }
        }
    }
}

// fp32 -> fp16, 8 elems/thread
__global__ __launch_bounds__(256)
void f32_to_f16(const float* __restrict__ src, __half* __restrict__ dst, int n8)
{
    int i = blockIdx.x * 256 + threadIdx.x;
    if (i < n8) {
        const float4 a = ((const float4*)src)[2 * i];
        const float4 b = ((const float4*)src)[2 * i + 1];
        uint4 o;
        half2 h;
        h = __floats2half2_rn(a.x, a.y); o.x = *(uint32_t*)&h;
        h = __floats2half2_rn(a.z, a.w); o.y = *(uint32_t*)&h;
        h = __floats2half2_rn(b.x, b.y); o.z = *(uint32_t*)&h;
        h = __floats2half2_rn(b.z, b.w); o.w = *(uint32_t*)&h;
        ((uint4*)dst)[i] = o;
    }
}

// fp32 -> tf32(rna)
__global__ __launch_bounds__(256)
void f32_to_tf32(const float* __restrict__ src, float* __restrict__ dst, int n4)
{
    int i = blockIdx.x * 256 + threadIdx.x;
    if (i < n4) {
        float4 v = ((const float4*)src)[i];
        v.x = f2tf(v.x); v.y = f2tf(v.y); v.z = f2tf(v.z); v.w = f2tf(v.w);
        ((float4*)dst)[i] = v;
    }
}

// softmax over rows of 2048 halfs; 256 threads, 8 halfs/thread
__global__ __launch_bounds__(256)
void softmax_h(__half* __restrict__ S)
{
    uint4* p = (uint4*)(S + (long long)blockIdx.x * SKVdim);
    const int tid = threadIdx.x, wid = tid >> 5, lane = tid & 31;
    __shared__ float red[8];

    uint4 v = p[tid];
    float f[8];
    { float2 t;
      t = __half22float2(*(half2*)&v.x); f[0]=t.x; f[1]=t.y;
      t = __half22float2(*(half2*)&v.y); f[2]=t.x; f[3]=t.y;
      t = __half22float2(*(half2*)&v.z); f[4]=t.x; f[5]=t.y;
      t = __half22float2(*(half2*)&v.w); f[6]=t.x; f[7]=t.y; }

    float m = f[0];
    #pragma unroll
    for (int j = 1; j < 8; j++) m = fmaxf(m, f[j]);
    #pragma unroll
    for (int o = 16; o > 0; o >>= 1) m = fmaxf(m, __shfl_xor_sync(~0u, m, o));
    if (lane == 0) red[wid] = m;
    __syncthreads();
    m = red[0];
    #pragma unroll
    for (int w = 1; w < 8; w++) m = fmaxf(m, red[w]);
    __syncthreads();

    float s = 0.f;
    #pragma unroll
    for (int j = 0; j < 8; j++) { f[j] = __expf(f[j] - m); s += f[j]; }
    #pragma unroll
    for (int o = 16; o > 0; o >>= 1) s += __shfl_xor_sync(~0u, s, o);
    if (lane == 0) red[wid] = s;
    __syncthreads();
    s = red[0] + red[1] + red[2] + red[3] + red[4] + red[5] + red[6] + red[7];

    const float inv = 1.0f / s;
    half2 h;
    h = __floats2half2_rn(f[0]*inv, f[1]*inv); v.x = *(uint32_t*)&h;
    h = __floats2half2_rn(f[2]*inv, f[3]*inv); v.y = *(uint32_t*)&h;
    h = __floats2half2_rn(f[4]*inv, f[5]*inv); v.z = *(uint32_t*)&h;
    h = __floats2half2_rn(f[6]*inv, f[7]*inv); v.w = *(uint32_t*)&h;
    p[tid] = v;
}

extern "C" void kernel_launch(void* const* d_in, const int* in_sizes, int n_in,
                              void* d_out, int out_size)
{
    const float* x  = (const float*)d_in[0];
    const float* ce = (const float*)d_in[1];
    const float* Wq = (const float*)d_in[2];
    const float* bq = (const float*)d_in[3];
    const float* Wk = (const float*)d_in[4];
    const float* bk = (const float*)d_in[5];
    const float* Wv = (const float*)d_in[6];
    const float* bv = (const float*)d_in[7];
    const float* Wo = (const float*)d_in[8];
    const float* bo = (const float*)d_in[9];
    float* out = (float*)d_out;

    __half *xh, *ceh, *Wqh, *Wkh, *Wvh, *Qh, *Kh, *Vth, *Sh;
    float *Wot, *At;
    cudaGetSymbolAddress((void**)&xh,  g_xh);
    cudaGetSymbolAddress((void**)&ceh, g_ceh);
    cudaGetSymbolAddress((void**)&Wqh, g_Wqh);
    cudaGetSymbolAddress((void**)&Wkh, g_Wkh);
    cudaGetSymbolAddress((void**)&Wvh, g_Wvh);
    cudaGetSymbolAddress((void**)&Wot, g_Wot);
    cudaGetSymbolAddress((void**)&Qh,  g_Qh);
    cudaGetSymbolAddress((void**)&Kh,  g_Kh);
    cudaGetSymbolAddress((void**)&Vth, g_Vth);
    cudaGetSymbolAddress((void**)&Sh,  g_Sh);
    cudaGetSymbolAddress((void**)&At,  g_At);

    #define SETSM(KF) cudaFuncSetAttribute(KF, cudaFuncAttributeMaxDynamicSharedMemorySize, SMEM_BYTES)
    SETSM((gemm_k<true , true , true , false, false, false, true >));   // QK merged
    SETSM((gemm_k<true , true , false, true , false, false, false>));   // Vt
    SETSM((gemm_k<true , true , false, false, false, false, false>));   // scores
    SETSM((gemm_k<true , false, false, false, true , true , false>));   // At
    SETSM((gemm_k<false, false, true , false, false, false, false>));   // final tf32

    dim3 blk(256);

    const int act8 = Mtot * Cdim / 8;
    const int w8   = Cdim * Cdim / 8;
    f32_to_f16<<<act8 / 256, 256>>>(x,  xh,  act8);
    f32_to_f16<<<act8 / 256, 256>>>(ce, ceh, act8);
    f32_to_f16<<<w8 / 256, 256>>>(Wq, Wqh, w8);
    f32_to_f16<<<w8 / 256, 256>>>(Wk, Wkh, w8);
    f32_to_f16<<<w8 / 256, 256>>>(Wv, Wvh, w8);
    f32_to_tf32<<<Cdim * Cdim / 4 / 256, 256>>>(Wo, Wot, Cdim * Cdim / 4);

    // Qh = xh @ Wqh^T + bq  AND  Kh = ceh @ Wkh^T + bk   (merged, z selects)
    gemm_k<true,true,true,false,false,false,true><<<dim3(Cdim/128, Mtot/128, 2), blk, SMEM_BYTES>>>(
        xh, Wqh, bq, nullptr, Qh, ceh, Wkh, bk, Kh,
        Cdim, Cdim, Cdim, Cdim/64, 0,0,0,0, 1.0f);
    // Vth = Wvh @ ceh^T + bv   -> [C, B*SKV]
    gemm_k<true,true,false,true,false,false,false><<<dim3(Mtot/128, Cdim/128, 1), blk, SMEM_BYTES>>>(
        Wvh, ceh, bv, nullptr, Vth, nullptr, nullptr, nullptr, nullptr,
        Cdim, Cdim, Mtot, Cdim/64, 0,0,0,0, 1.0f);
    // Sh = (Qh @ Kh^T) / 32
    gemm_k<true,true,false,false,false,false,false><<<dim3(SKVdim/128, SQdim/128, Bdim), blk, SMEM_BYTES>>>(
        Qh, Kh, nullptr, nullptr, Sh, nullptr, nullptr, nullptr, nullptr,
        Cdim, Cdim, SKVdim, Cdim/64,
        (long long)SQdim*Cdim, (long long)SKVdim*Cdim, (long long)SQdim*SKVdim, 0, 0.03125f);
    // Ph = softmax(Sh)
    softmax_h<<<Bdim * SQdim, 256>>>(Sh);
    // At = Ph @ Vth^T + x
    gemm_k<true,false,false,false,true,true,false><<<dim3(Cdim/128, SQdim/128, Bdim), blk, SMEM_BYTES>>>(
        Sh, Vth, nullptr, x, At, nullptr, nullptr, nullptr, nullptr,
        SKVdim, Mtot, Cdim, SKVdim/64,
        (long long)SQdim*SKVdim, (long long)SKVdim, (long long)SQdim*Cdim,
        (long long)SQdim*Cdim, 1.0f);
    // out = At @ Wot^T + bo (tf32)
    gemm_k<false,false,true,false,false,false,false><<<dim3(Cdim/128, Mtot/128, 1), blk, SMEM_BYTES>>>(
        At, Wot, bo, nullptr, out, nullptr, nullptr, nullptr, nullptr,
        Cdim, Cdim, Cdim, Cdim/32, 0,0,0,0, 1.0f);
}

// round 8
// speedup vs baseline: 3.2516x; 1.1172x over previous
#include <cuda_runtime.h>
#include <cuda_fp16.h>
#include <cstdint>

// ---------------------------------------------------------------------------
// SpatialTransformer R8: all-fp16 mma.sync (tf32 mantissa == fp16 mantissa, so
// the tf32 output projection was pure waste), 3-way merged projection launch.
//   xh,ceh,Wqh,Wkh,Wvh,Woh = fp16(inputs)
//   [merged z=0,1,2]:
//     Qh  = xh @ Wqh^T + bq        half out, bias-N
//     Kh  = ceh@ Wkh^T + bk        half out, bias-N
//     Vth = Wvh@ ceh^T + bv        half out, bias-M  -> [C, B*SKV]
//   Sh  = (Qh @ Kh^T)/32           half out, batched
//   Ph  = softmax_rows(Sh)
//   Ath = Ph @ Vth^T + x           half out, +Add(float x)
//   out = Ath @ Woh^T + bo         float out
// GEMM: 256 thr, 8 warps 64x32, 2 CTAs/SM, 3-stage cp.async, ldmatrix.x4.
// ---------------------------------------------------------------------------

#define Cdim  1024
#define Bdim  4
#define SQdim 2048
#define SKVdim 2048
#define Mtot  (Bdim * SQdim)            // 8192

__device__ __half g_xh [(long long)Mtot * Cdim];
__device__ __half g_ceh[(long long)Mtot * Cdim];
__device__ __half g_Wqh[(long long)Cdim * Cdim];
__device__ __half g_Wkh[(long long)Cdim * Cdim];
__device__ __half g_Wvh[(long long)Cdim * Cdim];
__device__ __half g_Woh[(long long)Cdim * Cdim];
__device__ __half g_Qh [(long long)Mtot * Cdim];
__device__ __half g_Kh [(long long)Mtot * Cdim];
__device__ __half g_Vth[(long long)Cdim * Mtot];
__device__ __half g_Sh [(long long)Bdim * SQdim * SKVdim];
__device__ __half g_Ath[(long long)Mtot * Cdim];

__device__ __forceinline__ void mma_f16(float* d, const uint32_t* a, const uint32_t* b){
    asm volatile("mma.sync.aligned.m16n8k16.row.col.f32.f16.f16.f32 "
        "{%0,%1,%2,%3}, {%4,%5,%6,%7}, {%8,%9}, {%0,%1,%2,%3};"
        : "+f"(d[0]), "+f"(d[1]), "+f"(d[2]), "+f"(d[3])
        : "r"(a[0]), "r"(a[1]), "r"(a[2]), "r"(a[3]), "r"(b[0]), "r"(b[1]));
}

#define LDM4(r0,r1,r2,r3,addr) \
  asm volatile("ldmatrix.sync.aligned.m8n8.x4.shared.b16 {%0,%1,%2,%3}, [%4];" \
    : "=r"(r0),"=r"(r1),"=r"(r2),"=r"(r3) : "r"(addr))

#define CPA16(dst, src) \
  asm volatile("cp.async.cg.shared.global [%0], [%1], 16;" :: "r"(dst), "l"(src))
#define CPA_COMMIT() asm volatile("cp.async.commit_group;" ::: "memory")
#define CPA_WAIT1()  asm volatile("cp.async.wait_group 1;" ::: "memory")
#define CPA_WAIT0()  asm volatile("cp.async.wait_group 0;" ::: "memory")

// Tile: 128 rows x (128B data + 16B pad) = 18432 B; A+B per stage = 36864 B
#define RSTR 144
#define TILEB 18432
#define BUFB  36864
#define SMEM_BYTES (BUFB * 3)          // 110592, 3 stages

// D[128x128] tile of scale*(A @ B^T) [+bias] [+Add].  All operands fp16, BK=64.
// HOUT: store half; else float.
// MG3: grid (8,64,3); z=0,1 -> (A0,B0,bias0,C0)/(A1,...) bias-N, m0=by,n0=bx;
//      z=2 -> (A2,...) bias-M, m0=bx, n0=by, ldc=ldc2.
// else: batched via blockIdx.z strides sA/sB/sC/sAdd.
template<bool HOUT, bool BN_, bool ADD_, bool MG3>
__global__ __launch_bounds__(256, 2)
void gemm_k(const __half* __restrict__ A0, const __half* __restrict__ B0,
            const float* __restrict__ bias0, void* __restrict__ C0,
            const __half* __restrict__ A1, const __half* __restrict__ B1,
            const float* __restrict__ bias1, void* __restrict__ C1,
            const __half* __restrict__ A2, const __half* __restrict__ B2,
            const float* __restrict__ bias2, void* __restrict__ C2,
            const float* __restrict__ Add,
            int lda, int ldb, int ldc, int ldc2, int NK,
            long long sA, long long sB, long long sC, long long sAdd,
            float scale)
{
    extern __shared__ char smem[];
    uint32_t sbase;
    asm("{ .reg .u64 t; cvta.to.shared.u64 t, %1; cvt.u32.u64 %0, t; }"
        : "=r"(sbase) : "l"(smem));

    const int tid = threadIdx.x, wid = tid >> 5, lane = tid & 31;

    const __half* A;
    const __half* B;
    const float* bias;
    void* Csel;
    int m0, n0;
    bool biasM = false;
    if (MG3) {
        const int z = blockIdx.z;
        if (z == 0)      { A = A0; B = B0; bias = bias0; Csel = C0; }
        else if (z == 1) { A = A1; B = B1; bias = bias1; Csel = C1; }
        else             { A = A2; B = B2; bias = bias2; Csel = C2; }
        if (z == 2) { m0 = blockIdx.x * 128; n0 = blockIdx.y * 128; ldc = ldc2; biasM = true; }
        else        { m0 = blockIdx.y * 128; n0 = blockIdx.x * 128; }
    } else {
        A = A0 + (long long)blockIdx.z * sA;
        B = B0 + (long long)blockIdx.z * sB;
        bias = bias0;
        Csel = C0;
        m0 = blockIdx.y * 128; n0 = blockIdx.x * 128;
        if (ADD_) Add += (long long)blockIdx.z * sAdd;
    }

    // ---- cp.async loader: 2 threads per row, 4x16B chunks each ----
    const int lrow = tid >> 1;
    const int lhalf = tid & 1;
    const __half* ap = A + (long long)(m0 + lrow) * lda + lhalf * 32;
    const __half* bp = B + (long long)(n0 + lrow) * ldb + lhalf * 32;
    const uint32_t aSt = sbase + lrow * RSTR + lhalf * 64;
    const uint32_t bSt = sbase + TILEB + lrow * RSTR + lhalf * 64;

    // ---- warp mapping: 8 warps, 64x32 each ----
    const int wm = (wid & 1) * 64;
    const int wn = (wid >> 1) * 32;
    const int qr = lane >> 2, qc = lane & 3;
    uint32_t aF[4], bF[2];
    #pragma unroll
    for (int mi = 0; mi < 4; mi++)
        aF[mi] = sbase + (wm + mi * 16 + (lane & 15)) * RSTR + (lane >> 4) * 16;
    #pragma unroll
    for (int nt = 0; nt < 2; nt++)
        bF[nt] = sbase + TILEB +
                 (wn + nt * 16 + (lane & 7) + ((lane >> 4) << 3)) * RSTR +
                 ((lane >> 3) & 1) * 16;

    float acc[4][4][4];
    #pragma unroll
    for (int mi = 0; mi < 4; mi++)
        #pragma unroll
        for (int nj = 0; nj < 4; nj++)
            #pragma unroll
            for (int j = 0; j < 4; j++) acc[mi][nj][j] = 0.f;

    // ---- prologue: tiles 0,1 -> stages 0,1 ----
    #pragma unroll
    for (int i = 0; i < 4; i++) CPA16(aSt + i * 16, ap + i * 8);
    #pragma unroll
    for (int i = 0; i < 4; i++) CPA16(bSt + i * 16, bp + i * 8);
    CPA_COMMIT();
    if (NK > 1) {
        #pragma unroll
        for (int i = 0; i < 4; i++) CPA16(aSt + BUFB + i * 16, ap + 64 + i * 8);
        #pragma unroll
        for (int i = 0; i < 4; i++) CPA16(bSt + BUFB + i * 16, bp + 64 + i * 8);
        CPA_COMMIT();
    }

    uint32_t bo_cur = 0;
    uint32_t bo_pre = 2 * BUFB;
    for (int k = 0; k < NK; k++) {
        if (k + 1 < NK) CPA_WAIT1(); else CPA_WAIT0();
        __syncthreads();
        if (k + 2 < NK) {
            const int k0 = (k + 2) * 64;
            #pragma unroll
            for (int i = 0; i < 4; i++) CPA16(aSt + bo_pre + i * 16, ap + k0 + i * 8);
            #pragma unroll
            for (int i = 0; i < 4; i++) CPA16(bSt + bo_pre + i * 16, bp + k0 + i * 8);
            CPA_COMMIT();
        }

        const uint32_t bo = bo_cur;
        #pragma unroll
        for (int s = 0; s < 4; s++) {
            uint32_t afr[4][4];
            #pragma unroll
            for (int mi = 0; mi < 4; mi++)
                LDM4(afr[mi][0], afr[mi][1], afr[mi][2], afr[mi][3],
                     aF[mi] + bo + s * 32);
            uint32_t bfr[4][2];
            #pragma unroll
            for (int nt = 0; nt < 2; nt++) {
                uint32_t t0, t1, t2, t3;
                LDM4(t0, t1, t2, t3, bF[nt] + bo + s * 32);
                bfr[nt * 2][0] = t0;     bfr[nt * 2][1] = t1;
                bfr[nt * 2 + 1][0] = t2; bfr[nt * 2 + 1][1] = t3;
            }
            #pragma unroll
            for (int mi = 0; mi < 4; mi++)
                #pragma unroll
                for (int nj = 0; nj < 4; nj++)
                    mma_f16(acc[mi][nj], afr[mi], bfr[nj]);
        }
        bo_pre = bo_cur;
        bo_cur = (bo_cur == 2 * BUFB) ? 0 : bo_cur + BUFB;
    }

    // ---- epilogue ----
    #pragma unroll
    for (int mi = 0; mi < 4; mi++) {
        #pragma unroll
        for (int h = 0; h < 2; h++) {
            const long long gm = m0 + wm + mi * 16 + qr + h * 8;
            float bm = 0.f;
            if (MG3) { if (biasM) bm = bias[gm]; }
            #pragma unroll
            for (int nj = 0; nj < 4; nj++) {
                const int gn = n0 + wn + nj * 8 + qc * 2;
                float vx = acc[mi][nj][h * 2 + 0] * scale;
                float vy = acc[mi][nj][h * 2 + 1] * scale;
                if (MG3) {
                    if (biasM) { vx += bm; vy += bm; }
                    else { const float2 bb = *(const float2*)(bias + gn); vx += bb.x; vy += bb.y; }
                } else if (BN_) {
                    const float2 bb = *(const float2*)(bias + gn); vx += bb.x; vy += bb.y;
                }
                if (ADD_) {
                    const float2 ad = *(const float2*)(Add + gm * ldc + gn);
                    vx += ad.x; vy += ad.y;
                }
                if (HOUT) {
                    __half* Co = (__half*)Csel + (MG3 ? 0ll : (long long)blockIdx.z * sC);
                    *(half2*)(Co + gm * ldc + gn) = __floats2half2_rn(vx, vy);
                } else {
                    float* Co = (float*)Csel + (MG3 ? 0ll : (long long)blockIdx.z * sC);
                    *(float2*)(Co + gm * ldc + gn) = make_float2(vx, vy);
                }
            }
        }
    }
}

// fp32 -> fp16, 8 elems/thread
__global__ __launch_bounds__(256)
void f32_to_f16(const float* __restrict__ src, __half* __restrict__ dst, int n8)
{
    int i = blockIdx.x * 256 + threadIdx.x;
    if (i < n8) {
        const float4 a = ((const float4*)src)[2 * i];
        const float4 b = ((const float4*)src)[2 * i + 1];
        uint4 o;
        half2 h;
        h = __floats2half2_rn(a.x, a.y); o.x = *(uint32_t*)&h;
        h = __floats2half2_rn(a.z, a.w); o.y = *(uint32_t*)&h;
        h = __floats2half2_rn(b.x, b.y); o.z = *(uint32_t*)&h;
        h = __floats2half2_rn(b.z, b.w); o.w = *(uint32_t*)&h;
        ((uint4*)dst)[i] = o;
    }
}

// softmax over rows of 2048 halfs; 256 threads, 8 halfs/thread
__global__ __launch_bounds__(256)
void softmax_h(__half* __restrict__ S)
{
    uint4* p = (uint4*)(S + (long long)blockIdx.x * SKVdim);
    const int tid = threadIdx.x, wid = tid >> 5, lane = tid & 31;
    __shared__ float red[8];

    uint4 v = p[tid];
    float f[8];
    { float2 t;
      t = __half22float2(*(half2*)&v.x); f[0]=t.x; f[1]=t.y;
      t = __half22float2(*(half2*)&v.y); f[2]=t.x; f[3]=t.y;
      t = __half22float2(*(half2*)&v.z); f[4]=t.x; f[5]=t.y;
      t = __half22float2(*(half2*)&v.w); f[6]=t.x; f[7]=t.y; }

    float m = f[0];
    #pragma unroll
    for (int j = 1; j < 8; j++) m = fmaxf(m, f[j]);
    #pragma unroll
    for (int o = 16; o > 0; o >>= 1) m = fmaxf(m, __shfl_xor_sync(~0u, m, o));
    if (lane == 0) red[wid] = m;
    __syncthreads();
    m = red[0];
    #pragma unroll
    for (int w = 1; w < 8; w++) m = fmaxf(m, red[w]);
    __syncthreads();

    float s = 0.f;
    #pragma unroll
    for (int j = 0; j < 8; j++) { f[j] = __expf(f[j] - m); s += f[j]; }
    #pragma unroll
    for (int o = 16; o > 0; o >>= 1) s += __shfl_xor_sync(~0u, s, o);
    if (lane == 0) red[wid] = s;
    __syncthreads();
    s = red[0] + red[1] + red[2] + red[3] + red[4] + red[5] + red[6] + red[7];

    const float inv = 1.0f / s;
    half2 h;
    h = __floats2half2_rn(f[0]*inv, f[1]*inv); v.x = *(uint32_t*)&h;
    h = __floats2half2_rn(f[2]*inv, f[3]*inv); v.y = *(uint32_t*)&h;
    h = __floats2half2_rn(f[4]*inv, f[5]*inv); v.z = *(uint32_t*)&h;
    h = __floats2half2_rn(f[6]*inv, f[7]*inv); v.w = *(uint32_t*)&h;
    p[tid] = v;
}

extern "C" void kernel_launch(void* const* d_in, const int* in_sizes, int n_in,
                              void* d_out, int out_size)
{
    const float* x  = (const float*)d_in[0];
    const float* ce = (const float*)d_in[1];
    const float* Wq = (const float*)d_in[2];
    const float* bq = (const float*)d_in[3];
    const float* Wk = (const float*)d_in[4];
    const float* bk = (const float*)d_in[5];
    const float* Wv = (const float*)d_in[6];
    const float* bv = (const float*)d_in[7];
    const float* Wo = (const float*)d_in[8];
    const float* bo = (const float*)d_in[9];
    float* out = (float*)d_out;

    __half *xh, *ceh, *Wqh, *Wkh, *Wvh, *Woh, *Qh, *Kh, *Vth, *Sh, *Ath;
    cudaGetSymbolAddress((void**)&xh,  g_xh);
    cudaGetSymbolAddress((void**)&ceh, g_ceh);
    cudaGetSymbolAddress((void**)&Wqh, g_Wqh);
    cudaGetSymbolAddress((void**)&Wkh, g_Wkh);
    cudaGetSymbolAddress((void**)&Wvh, g_Wvh);
    cudaGetSymbolAddress((void**)&Woh, g_Woh);
    cudaGetSymbolAddress((void**)&Qh,  g_Qh);
    cudaGetSymbolAddress((void**)&Kh,  g_Kh);
    cudaGetSymbolAddress((void**)&Vth, g_Vth);
    cudaGetSymbolAddress((void**)&Sh,  g_Sh);
    cudaGetSymbolAddress((void**)&Ath, g_Ath);

    #define SETSM(KF) cudaFuncSetAttribute(KF, cudaFuncAttributeMaxDynamicSharedMemorySize, SMEM_BYTES)
    SETSM((gemm_k<true , false, false, true >));   // merged projections
    SETSM((gemm_k<true , false, false, false>));   // scores
    SETSM((gemm_k<true , false, true , false>));   // At (+residual)
    SETSM((gemm_k<false, true , false, false>));   // final

    dim3 blk(256);

    const int act8 = Mtot * Cdim / 8;
    const int w8   = Cdim * Cdim / 8;
    f32_to_f16<<<act8 / 256, 256>>>(x,  xh,  act8);
    f32_to_f16<<<act8 / 256, 256>>>(ce, ceh, act8);
    f32_to_f16<<<w8 / 256, 256>>>(Wq, Wqh, w8);
    f32_to_f16<<<w8 / 256, 256>>>(Wk, Wkh, w8);
    f32_to_f16<<<w8 / 256, 256>>>(Wv, Wvh, w8);
    f32_to_f16<<<w8 / 256, 256>>>(Wo, Woh, w8);

    // merged: z=0 Qh = xh@Wqh^T+bq; z=1 Kh = ceh@Wkh^T+bk; z=2 Vth = Wvh@ceh^T+bv
    gemm_k<true,false,false,true><<<dim3(Cdim/128, Mtot/128, 3), blk, SMEM_BYTES>>>(
        xh,  Wqh, bq, Qh,
        ceh, Wkh, bk, Kh,
        Wvh, ceh, bv, Vth,
        nullptr, Cdim, Cdim, Cdim, Mtot, Cdim/64, 0,0,0,0, 1.0f);
    // Sh = (Qh @ Kh^T) / 32
    gemm_k<true,false,false,false><<<dim3(SKVdim/128, SQdim/128, Bdim), blk, SMEM_BYTES>>>(
        Qh, Kh, nullptr, Sh,
        nullptr, nullptr, nullptr, nullptr,
        nullptr, nullptr, nullptr, nullptr,
        nullptr, Cdim, Cdim, SKVdim, 0, Cdim/64,
        (long long)SQdim*Cdim, (long long)SKVdim*Cdim, (long long)SQdim*SKVdim, 0, 0.03125f);
    // Ph = softmax(Sh)
    softmax_h<<<Bdim * SQdim, 256>>>(Sh);
    // Ath = Ph @ Vth^T + x   (half out)
    gemm_k<true,false,true,false><<<dim3(Cdim/128, SQdim/128, Bdim), blk, SMEM_BYTES>>>(
        Sh, Vth, nullptr, Ath,
        nullptr, nullptr, nullptr, nullptr,
        nullptr, nullptr, nullptr, nullptr,
        x, SKVdim, Mtot, Cdim, 0, SKVdim/64,
        (long long)SQdim*SKVdim, (long long)SKVdim, (long long)SQdim*Cdim,
        (long long)SQdim*Cdim, 1.0f);
    // out = Ath @ Woh^T + bo  (float out)
    gemm_k<false,true,false,false><<<dim3(Cdim/128, Mtot/128, 1), blk, SMEM_BYTES>>>(
        Ath, Woh, bo, out,
        nullptr, nullptr, nullptr, nullptr,
        nullptr, nullptr, nullptr, nullptr,
        nullptr, Cdim, Cdim, Cdim, 0, Cdim/64, 0,0,0,0, 1.0f);
}

// round 9
// speedup vs baseline: 3.3120x; 1.0186x over previous
#include <cuda_runtime.h>
#include <cuda_fp16.h>
#include <cstdint>

// ---------------------------------------------------------------------------
// SpatialTransformer R9: R8 all-fp16 pipeline + single fused cvt kernel
// (fewer launches, less tail; ncu -s 5 now lands on the final GEMM).
//   cvt_all: xh,ceh,Wqh,Wkh,Wvh,Woh = fp16(inputs)       [1 launch]
//   merged z=0,1,2: Qh,Kh (bias-N) / Vth (bias-M, [C,B*SKV])
//   Sh  = (Qh @ Kh^T)/32           half out, batched
//   Ph  = softmax_rows(Sh)
//   Ath = Ph @ Vth^T + x           half out, +Add(float x)
//   out = Ath @ Woh^T + bo         float out
// GEMM: 256 thr, 8 warps 64x32, 2 CTAs/SM, 3-stage cp.async, ldmatrix.x4.
// ---------------------------------------------------------------------------

#define Cdim  1024
#define Bdim  4
#define SQdim 2048
#define SKVdim 2048
#define Mtot  (Bdim * SQdim)            // 8192

__device__ __half g_xh [(long long)Mtot * Cdim];
__device__ __half g_ceh[(long long)Mtot * Cdim];
__device__ __half g_Wqh[(long long)Cdim * Cdim];
__device__ __half g_Wkh[(long long)Cdim * Cdim];
__device__ __half g_Wvh[(long long)Cdim * Cdim];
__device__ __half g_Woh[(long long)Cdim * Cdim];
__device__ __half g_Qh [(long long)Mtot * Cdim];
__device__ __half g_Kh [(long long)Mtot * Cdim];
__device__ __half g_Vth[(long long)Cdim * Mtot];
__device__ __half g_Sh [(long long)Bdim * SQdim * SKVdim];
__device__ __half g_Ath[(long long)Mtot * Cdim];

__device__ __forceinline__ void mma_f16(float* d, const uint32_t* a, const uint32_t* b){
    asm volatile("mma.sync.aligned.m16n8k16.row.col.f32.f16.f16.f32 "
        "{%0,%1,%2,%3}, {%4,%5,%6,%7}, {%8,%9}, {%0,%1,%2,%3};"
        : "+f"(d[0]), "+f"(d[1]), "+f"(d[2]), "+f"(d[3])
        : "r"(a[0]), "r"(a[1]), "r"(a[2]), "r"(a[3]), "r"(b[0]), "r"(b[1]));
}

#define LDM4(r0,r1,r2,r3,addr) \
  asm volatile("ldmatrix.sync.aligned.m8n8.x4.shared.b16 {%0,%1,%2,%3}, [%4];" \
    : "=r"(r0),"=r"(r1),"=r"(r2),"=r"(r3) : "r"(addr))

#define CPA16(dst, src) \
  asm volatile("cp.async.cg.shared.global [%0], [%1], 16;" :: "r"(dst), "l"(src))
#define CPA_COMMIT() asm volatile("cp.async.commit_group;" ::: "memory")
#define CPA_WAIT1()  asm volatile("cp.async.wait_group 1;" ::: "memory")
#define CPA_WAIT0()  asm volatile("cp.async.wait_group 0;" ::: "memory")

// Tile: 128 rows x (128B data + 16B pad) = 18432 B; A+B per stage = 36864 B
#define RSTR 144
#define TILEB 18432
#define BUFB  36864
#define SMEM_BYTES (BUFB * 3)          // 110592, 3 stages

// D[128x128] tile of scale*(A @ B^T) [+bias] [+Add].  All operands fp16, BK=64.
// HOUT: store half; else float.
// MG3: grid (8,64,3); z=0,1 -> set0/set1, bias-N, m0=by,n0=bx;
//      z=2 -> set2, bias-M, m0=bx, n0=by, ldc=ldc2.
// else: batched via blockIdx.z strides sA/sB/sC/sAdd.
template<bool HOUT, bool BN_, bool ADD_, bool MG3>
__global__ __launch_bounds__(256, 2)
void gemm_k(const __half* __restrict__ A0, const __half* __restrict__ B0,
            const float* __restrict__ bias0, void* __restrict__ C0,
            const __half* __restrict__ A1, const __half* __restrict__ B1,
            const float* __restrict__ bias1, void* __restrict__ C1,
            const __half* __restrict__ A2, const __half* __restrict__ B2,
            const float* __restrict__ bias2, void* __restrict__ C2,
            const float* __restrict__ Add,
            int lda, int ldb, int ldc, int ldc2, int NK,
            long long sA, long long sB, long long sC, long long sAdd,
            float scale)
{
    extern __shared__ char smem[];
    uint32_t sbase;
    asm("{ .reg .u64 t; cvta.to.shared.u64 t, %1; cvt.u32.u64 %0, t; }"
        : "=r"(sbase) : "l"(smem));

    const int tid = threadIdx.x, wid = tid >> 5, lane = tid & 31;

    const __half* A;
    const __half* B;
    const float* bias;
    void* Csel;
    int m0, n0;
    bool biasM = false;
    if (MG3) {
        const int z = blockIdx.z;
        if (z == 0)      { A = A0; B = B0; bias = bias0; Csel = C0; }
        else if (z == 1) { A = A1; B = B1; bias = bias1; Csel = C1; }
        else             { A = A2; B = B2; bias = bias2; Csel = C2; }
        if (z == 2) { m0 = blockIdx.x * 128; n0 = blockIdx.y * 128; ldc = ldc2; biasM = true; }
        else        { m0 = blockIdx.y * 128; n0 = blockIdx.x * 128; }
    } else {
        A = A0 + (long long)blockIdx.z * sA;
        B = B0 + (long long)blockIdx.z * sB;
        bias = bias0;
        Csel = C0;
        m0 = blockIdx.y * 128; n0 = blockIdx.x * 128;
        if (ADD_) Add += (long long)blockIdx.z * sAdd;
    }

    // ---- cp.async loader: 2 threads per row, 4x16B chunks each ----
    const int lrow = tid >> 1;
    const int lhalf = tid & 1;
    const __half* ap = A + (long long)(m0 + lrow) * lda + lhalf * 32;
    const __half* bp = B + (long long)(n0 + lrow) * ldb + lhalf * 32;
    const uint32_t aSt = sbase + lrow * RSTR + lhalf * 64;
    const uint32_t bSt = sbase + TILEB + lrow * RSTR + lhalf * 64;

    // ---- warp mapping: 8 warps, 64x32 each ----
    const int wm = (wid & 1) * 64;
    const int wn = (wid >> 1) * 32;
    const int qr = lane >> 2, qc = lane & 3;
    uint32_t aF[4], bF[2];
    #pragma unroll
    for (int mi = 0; mi < 4; mi++)
        aF[mi] = sbase + (wm + mi * 16 + (lane & 15)) * RSTR + (lane >> 4) * 16;
    #pragma unroll
    for (int nt = 0; nt < 2; nt++)
        bF[nt] = sbase + TILEB +
                 (wn + nt * 16 + (lane & 7) + ((lane >> 4) << 3)) * RSTR +
                 ((lane >> 3) & 1) * 16;

    float acc[4][4][4];
    #pragma unroll
    for (int mi = 0; mi < 4; mi++)
        #pragma unroll
        for (int nj = 0; nj < 4; nj++)
            #pragma unroll
            for (int j = 0; j < 4; j++) acc[mi][nj][j] = 0.f;

    // ---- prologue: tiles 0,1 -> stages 0,1 ----
    #pragma unroll
    for (int i = 0; i < 4; i++) CPA16(aSt + i * 16, ap + i * 8);
    #pragma unroll
    for (int i = 0; i < 4; i++) CPA16(bSt + i * 16, bp + i * 8);
    CPA_COMMIT();
    if (NK > 1) {
        #pragma unroll
        for (int i = 0; i < 4; i++) CPA16(aSt + BUFB + i * 16, ap + 64 + i * 8);
        #pragma unroll
        for (int i = 0; i < 4; i++) CPA16(bSt + BUFB + i * 16, bp + 64 + i * 8);
        CPA_COMMIT();
    }

    uint32_t bo_cur = 0;
    uint32_t bo_pre = 2 * BUFB;
    for (int k = 0; k < NK; k++) {
        if (k + 1 < NK) CPA_WAIT1(); else CPA_WAIT0();
        __syncthreads();
        if (k + 2 < NK) {
            const int k0 = (k + 2) * 64;
            #pragma unroll
            for (int i = 0; i < 4; i++) CPA16(aSt + bo_pre + i * 16, ap + k0 + i * 8);
            #pragma unroll
            for (int i = 0; i < 4; i++) CPA16(bSt + bo_pre + i * 16, bp + k0 + i * 8);
            CPA_COMMIT();
        }

        const uint32_t bo = bo_cur;
        #pragma unroll
        for (int s = 0; s < 4; s++) {
            uint32_t afr[4][4];
            #pragma unroll
            for (int mi = 0; mi < 4; mi++)
                LDM4(afr[mi][0], afr[mi][1], afr[mi][2], afr[mi][3],
                     aF[mi] + bo + s * 32);
            uint32_t bfr[4][2];
            #pragma unroll
            for (int nt = 0; nt < 2; nt++) {
                uint32_t t0, t1, t2, t3;
                LDM4(t0, t1, t2, t3, bF[nt] + bo + s * 32);
                bfr[nt * 2][0] = t0;     bfr[nt * 2][1] = t1;
                bfr[nt * 2 + 1][0] = t2; bfr[nt * 2 + 1][1] = t3;
            }
            #pragma unroll
            for (int mi = 0; mi < 4; mi++)
                #pragma unroll
                for (int nj = 0; nj < 4; nj++)
                    mma_f16(acc[mi][nj], afr[mi], bfr[nj]);
        }
        bo_pre = bo_cur;
        bo_cur = (bo_cur == 2 * BUFB) ? 0 : bo_cur + BUFB;
    }

    // ---- epilogue ----
    #pragma unroll
    for (int mi = 0; mi < 4; mi++) {
        #pragma unroll
        for (int h = 0; h < 2; h++) {
            const long long gm = m0 + wm + mi * 16 + qr + h * 8;
            float bm = 0.f;
            if (MG3) { if (biasM) bm = bias[gm]; }
            #pragma unroll
            for (int nj = 0; nj < 4; nj++) {
                const int gn = n0 + wn + nj * 8 + qc * 2;
                float vx = acc[mi][nj][h * 2 + 0] * scale;
                float vy = acc[mi][nj][h * 2 + 1] * scale;
                if (MG3) {
                    if (biasM) { vx += bm; vy += bm; }
                    else { const float2 bb = *(const float2*)(bias + gn); vx += bb.x; vy += bb.y; }
                } else if (BN_) {
                    const float2 bb = *(const float2*)(bias + gn); vx += bb.x; vy += bb.y;
                }
                if (ADD_) {
                    const float2 ad = *(const float2*)(Add + gm * ldc + gn);
                    vx += ad.x; vy += ad.y;
                }
                if (HOUT) {
                    __half* Co = (__half*)Csel + (MG3 ? 0ll : (long long)blockIdx.z * sC);
                    *(half2*)(Co + gm * ldc + gn) = __floats2half2_rn(vx, vy);
                } else {
                    float* Co = (float*)Csel + (MG3 ? 0ll : (long long)blockIdx.z * sC);
                    *(float2*)(Co + gm * ldc + gn) = make_float2(vx, vy);
                }
            }
        }
    }
}

// One fused fp32->fp16 conversion over all six tensors (grid-stride, 8 elems/iter)
#define ACT8 (Mtot * Cdim / 8)          // 1048576
#define W8   (Cdim * Cdim / 8)          // 131072
#define TOT8 (2 * ACT8 + 4 * W8)        // 2621440
__global__ __launch_bounds__(256)
void cvt_all(const float* __restrict__ x,  const float* __restrict__ ce,
             const float* __restrict__ Wq, const float* __restrict__ Wk,
             const float* __restrict__ Wv, const float* __restrict__ Wo,
             __half* __restrict__ xh,  __half* __restrict__ ceh,
             __half* __restrict__ Wqh, __half* __restrict__ Wkh,
             __half* __restrict__ Wvh, __half* __restrict__ Woh)
{
    for (int i = blockIdx.x * 256 + threadIdx.x; i < TOT8; i += gridDim.x * 256) {
        const float* s;
        __half* d;
        int j = i;
        if (j < ACT8)                 { s = x;  d = xh;  }
        else if ((j -= ACT8) < ACT8)  { s = ce; d = ceh; }
        else if ((j -= ACT8) < W8)    { s = Wq; d = Wqh; }
        else if ((j -= W8) < W8)      { s = Wk; d = Wkh; }
        else if ((j -= W8) < W8)      { s = Wv; d = Wvh; }
        else                          { j -= W8; s = Wo; d = Woh; }
        const float4 a = ((const float4*)s)[2 * j];
        const float4 b = ((const float4*)s)[2 * j + 1];
        uint4 o;
        half2 h;
        h = __floats2half2_rn(a.x, a.y); o.x = *(uint32_t*)&h;
        h = __floats2half2_rn(a.z, a.w); o.y = *(uint32_t*)&h;
        h = __floats2half2_rn(b.x, b.y); o.z = *(uint32_t*)&h;
        h = __floats2half2_rn(b.z, b.w); o.w = *(uint32_t*)&h;
        ((uint4*)d)[j] = o;
    }
}

// softmax over rows of 2048 halfs; 256 threads, 8 halfs/thread
__global__ __launch_bounds__(256)
void softmax_h(__half* __restrict__ S)
{
    uint4* p = (uint4*)(S + (long long)blockIdx.x * SKVdim);
    const int tid = threadIdx.x, wid = tid >> 5, lane = tid & 31;
    __shared__ float red[8];

    uint4 v = p[tid];
    float f[8];
    { float2 t;
      t = __half22float2(*(half2*)&v.x); f[0]=t.x; f[1]=t.y;
      t = __half22float2(*(half2*)&v.y); f[2]=t.x; f[3]=t.y;
      t = __half22float2(*(half2*)&v.z); f[4]=t.x; f[5]=t.y;
      t = __half22float2(*(half2*)&v.w); f[6]=t.x; f[7]=t.y; }

    float m = f[0];
    #pragma unroll
    for (int j = 1; j < 8; j++) m = fmaxf(m, f[j]);
    #pragma unroll
    for (int o = 16; o > 0; o >>= 1) m = fmaxf(m, __shfl_xor_sync(~0u, m, o));
    if (lane == 0) red[wid] = m;
    __syncthreads();
    m = red[0];
    #pragma unroll
    for (int w = 1; w < 8; w++) m = fmaxf(m, red[w]);
    __syncthreads();

    float s = 0.f;
    #pragma unroll
    for (int j = 0; j < 8; j++) { f[j] = __expf(f[j] - m); s += f[j]; }
    #pragma unroll
    for (int o = 16; o > 0; o >>= 1) s += __shfl_xor_sync(~0u, s, o);
    if (lane == 0) red[wid] = s;
    __syncthreads();
    s = red[0] + red[1] + red[2] + red[3] + red[4] + red[5] + red[6] + red[7];

    const float inv = 1.0f / s;
    half2 h;
    h = __floats2half2_rn(f[0]*inv, f[1]*inv); v.x = *(uint32_t*)&h;
    h = __floats2half2_rn(f[2]*inv, f[3]*inv); v.y = *(uint32_t*)&h;
    h = __floats2half2_rn(f[4]*inv, f[5]*inv); v.z = *(uint32_t*)&h;
    h = __floats2half2_rn(f[6]*inv, f[7]*inv); v.w = *(uint32_t*)&h;
    p[tid] = v;
}

extern "C" void kernel_launch(void* const* d_in, const int* in_sizes, int n_in,
                              void* d_out, int out_size)
{
    const float* x  = (const float*)d_in[0];
    const float* ce = (const float*)d_in[1];
    const float* Wq = (const float*)d_in[2];
    const float* bq = (const float*)d_in[3];
    const float* Wk = (const float*)d_in[4];
    const float* bk = (const float*)d_in[5];
    const float* Wv = (const float*)d_in[6];
    const float* bv = (const float*)d_in[7];
    const float* Wo = (const float*)d_in[8];
    const float* bo = (const float*)d_in[9];
    float* out = (float*)d_out;

    __half *xh, *ceh, *Wqh, *Wkh, *Wvh, *Woh, *Qh, *Kh, *Vth, *Sh, *Ath;
    cudaGetSymbolAddress((void**)&xh,  g_xh);
    cudaGetSymbolAddress((void**)&ceh, g_ceh);
    cudaGetSymbolAddress((void**)&Wqh, g_Wqh);
    cudaGetSymbolAddress((void**)&Wkh, g_Wkh);
    cudaGetSymbolAddress((void**)&Wvh, g_Wvh);
    cudaGetSymbolAddress((void**)&Woh, g_Woh);
    cudaGetSymbolAddress((void**)&Qh,  g_Qh);
    cudaGetSymbolAddress((void**)&Kh,  g_Kh);
    cudaGetSymbolAddress((void**)&Vth, g_Vth);
    cudaGetSymbolAddress((void**)&Sh,  g_Sh);
    cudaGetSymbolAddress((void**)&Ath, g_Ath);

    #define SETSM(KF) cudaFuncSetAttribute(KF, cudaFuncAttributeMaxDynamicSharedMemorySize, SMEM_BYTES)
    SETSM((gemm_k<true , false, false, true >));   // merged projections
    SETSM((gemm_k<true , false, false, false>));   // scores
    SETSM((gemm_k<true , false, true , false>));   // At (+residual)
    SETSM((gemm_k<false, true , false, false>));   // final

    dim3 blk(256);

    // 1: all dtype conversions in one grid-stride launch
    cvt_all<<<1184, 256>>>(x, ce, Wq, Wk, Wv, Wo, xh, ceh, Wqh, Wkh, Wvh, Woh);

    // 2: merged z=0 Qh=xh@Wqh^T+bq; z=1 Kh=ceh@Wkh^T+bk; z=2 Vth=Wvh@ceh^T+bv
    gemm_k<true,false,false,true><<<dim3(Cdim/128, Mtot/128, 3), blk, SMEM_BYTES>>>(
        xh,  Wqh, bq, Qh,
        ceh, Wkh, bk, Kh,
        Wvh, ceh, bv, Vth,
        nullptr, Cdim, Cdim, Cdim, Mtot, Cdim/64, 0,0,0,0, 1.0f);
    // 3: Sh = (Qh @ Kh^T) / 32
    gemm_k<true,false,false,false><<<dim3(SKVdim/128, SQdim/128, Bdim), blk, SMEM_BYTES>>>(
        Qh, Kh, nullptr, Sh,
        nullptr, nullptr, nullptr, nullptr,
        nullptr, nullptr, nullptr, nullptr,
        nullptr, Cdim, Cdim, SKVdim, 0, Cdim/64,
        (long long)SQdim*Cdim, (long long)SKVdim*Cdim, (long long)SQdim*SKVdim, 0, 0.03125f);
    // 4: Ph = softmax(Sh)
    softmax_h<<<Bdim * SQdim, 256>>>(Sh);
    // 5: Ath = Ph @ Vth^T + x   (half out)
    gemm_k<true,false,true,false><<<dim3(Cdim/128, SQdim/128, Bdim), blk, SMEM_BYTES>>>(
        Sh, Vth, nullptr, Ath,
        nullptr, nullptr, nullptr, nullptr,
        nullptr, nullptr, nullptr, nullptr,
        x, SKVdim, Mtot, Cdim, 0, SKVdim/64,
        (long long)SQdim*SKVdim, (long long)SKVdim, (long long)SQdim*Cdim,
        (long long)SQdim*Cdim, 1.0f);
    // 6: out = Ath @ Woh^T + bo  (float out) — ncu -s 5 captures this one
    gemm_k<false,true,false,false><<<dim3(Cdim/128, Mtot/128, 1), blk, SMEM_BYTES>>>(
        Ath, Woh, bo, out,
        nullptr, nullptr, nullptr, nullptr,
        nullptr, nullptr, nullptr, nullptr,
        nullptr, Cdim, Cdim, Cdim, 0, Cdim/64, 0,0,0,0, 1.0f);
}

// round 11
// speedup vs baseline: 4.0314x; 1.2172x over previous
#include <cuda_runtime.h>
#include <cuda_fp16.h>
#include <cstdint>

// ---------------------------------------------------------------------------
// SpatialTransformer R10: R9 all-fp16 pipeline, but the GEMM mainloop's
// __syncthreads-per-k-tile rendezvous is replaced by a 3-stage mbarrier
// producer/consumer pipeline (cp.async.mbarrier.arrive.noinc tracks data
// readiness; per-stage empty barriers give one full k-tile of slack, so
// warp skew is absorbed instead of serialized).
//   cvt_all -> merged proj (Q,K,Vt) -> scores -> softmax -> At -> final
// ---------------------------------------------------------------------------

#define Cdim  1024
#define Bdim  4
#define SQdim 2048
#define SKVdim 2048
#define Mtot  (Bdim * SQdim)            // 8192

__device__ __half g_xh [(long long)Mtot * Cdim];
__device__ __half g_ceh[(long long)Mtot * Cdim];
__device__ __half g_Wqh[(long long)Cdim * Cdim];
__device__ __half g_Wkh[(long long)Cdim * Cdim];
__device__ __half g_Wvh[(long long)Cdim * Cdim];
__device__ __half g_Woh[(long long)Cdim * Cdim];
__device__ __half g_Qh [(long long)Mtot * Cdim];
__device__ __half g_Kh [(long long)Mtot * Cdim];
__device__ __half g_Vth[(long long)Cdim * Mtot];
__device__ __half g_Sh [(long long)Bdim * SQdim * SKVdim];
__device__ __half g_Ath[(long long)Mtot * Cdim];

__device__ __forceinline__ void mma_f16(float* d, const uint32_t* a, const uint32_t* b){
    asm volatile("mma.sync.aligned.m16n8k16.row.col.f32.f16.f16.f32 "
        "{%0,%1,%2,%3}, {%4,%5,%6,%7}, {%8,%9}, {%0,%1,%2,%3};"
        : "+f"(d[0]), "+f"(d[1]), "+f"(d[2]), "+f"(d[3])
        : "r"(a[0]), "r"(a[1]), "r"(a[2]), "r"(a[3]), "r"(b[0]), "r"(b[1]));
}

#define LDM4(r0,r1,r2,r3,addr) \
  asm volatile("ldmatrix.sync.aligned.m8n8.x4.shared.b16 {%0,%1,%2,%3}, [%4];" \
    : "=r"(r0),"=r"(r1),"=r"(r2),"=r"(r3) : "r"(addr))

#define CPA16(dst, src) \
  asm volatile("cp.async.cg.shared.global [%0], [%1], 16;" :: "r"(dst), "l"(src))

#define MBAR_INIT(a,c) \
  asm volatile("mbarrier.init.shared.b64 [%0], %1;" :: "r"(a), "r"(c) : "memory")
#define MBAR_ARRIVE(a) \
  asm volatile("mbarrier.arrive.shared.b64 _, [%0];" :: "r"(a) : "memory")
#define CPA_MBAR_ARRIVE(a) \
  asm volatile("cp.async.mbarrier.arrive.noinc.shared.b64 [%0];" :: "r"(a) : "memory")

// blocks until mbarrier phase `ph` completes (acquire)
#define MBAR_WAIT(a, ph) do { uint32_t _m=(a); uint32_t _p=(ph); uint32_t _d; \
  asm volatile("{\n\t.reg .pred p;\n\tmbarrier.try_wait.parity.acquire.cta.shared::cta.b64 p, [%1], %2;\n\tselp.b32 %0,1,0,p;\n\t}" \
      : "=r"(_d) : "r"(_m), "r"(_p) : "memory"); \
  if(!_d){ asm volatile("{\n\t.reg .pred P1;\n\tWL_%=:\n\tmbarrier.try_wait.parity.acquire.cta.shared::cta.b64 P1, [%0], %1, 0x989680;\n\t@P1 bra.uni WD_%=;\n\tbra.uni WL_%=;\n\tWD_%=:\n\t}" \
      :: "r"(_m), "r"(_p) : "memory"); } } while(0)

// Tile: 128 rows x (128B data + 16B pad) = 18432 B; A+B per stage = 36864 B
#define RSTR 144
#define TILEB 18432
#define BUFB  36864
#define MB_OFF (BUFB * 3)              // 110592: full[0..2] @ +0,+8,+16; empty @ +24,+32,+40
#define SMEM_BYTES (MB_OFF + 64)       // 110656

// D[128x128] tile of scale*(A @ B^T) [+bias] [+Add].  All operands fp16, BK=64.
// HOUT: store half; else float.
// MG3: grid (8,64,3); z=0,1 -> set0/set1, bias-N, m0=by,n0=bx;
//      z=2 -> set2, bias-M, m0=bx, n0=by, ldc=ldc2.
// else: batched via blockIdx.z strides sA/sB/sC/sAdd.
template<bool HOUT, bool BN_, bool ADD_, bool MG3>
__global__ __launch_bounds__(256, 2)
void gemm_k(const __half* __restrict__ A0, const __half* __restrict__ B0,
            const float* __restrict__ bias0, void* __restrict__ C0,
            const __half* __restrict__ A1, const __half* __restrict__ B1,
            const float* __restrict__ bias1, void* __restrict__ C1,
            const __half* __restrict__ A2, const __half* __restrict__ B2,
            const float* __restrict__ bias2, void* __restrict__ C2,
            const float* __restrict__ Add,
            int lda, int ldb, int ldc, int ldc2, int NK,
            long long sA, long long sB, long long sC, long long sAdd,
            float scale)
{
    extern __shared__ char smem[];
    uint32_t sbase;
    asm("{ .reg .u64 t; cvta.to.shared.u64 t, %1; cvt.u32.u64 %0, t; }"
        : "=r"(sbase) : "l"(smem));

    const int tid = threadIdx.x, wid = tid >> 5, lane = tid & 31;

    const __half* A;
    const __half* B;
    const float* bias;
    void* Csel;
    int m0, n0;
    bool biasM = false;
    if (MG3) {
        const int z = blockIdx.z;
        if (z == 0)      { A = A0; B = B0; bias = bias0; Csel = C0; }
        else if (z == 1) { A = A1; B = B1; bias = bias1; Csel = C1; }
        else             { A = A2; B = B2; bias = bias2; Csel = C2; }
        if (z == 2) { m0 = blockIdx.x * 128; n0 = blockIdx.y * 128; ldc = ldc2; biasM = true; }
        else        { m0 = blockIdx.y * 128; n0 = blockIdx.x * 128; }
    } else {
        A = A0 + (long long)blockIdx.z * sA;
        B = B0 + (long long)blockIdx.z * sB;
        bias = bias0;
        Csel = C0;
        m0 = blockIdx.y * 128; n0 = blockIdx.x * 128;
        if (ADD_) Add += (long long)blockIdx.z * sAdd;
    }

    // ---- mbarrier setup: full[s] (cp.async completion), empty[s] (consumers) ----
    const uint32_t mb = sbase + MB_OFF;
    if (tid == 0) {
        #pragma unroll
        for (int s = 0; s < 3; s++) {
            MBAR_INIT(mb + s * 8, 256);        // full[s]
            MBAR_INIT(mb + 24 + s * 8, 256);   // empty[s]
        }
    }
    __syncthreads();

    // ---- cp.async loader: 2 threads per row, 4x16B chunks each ----
    const int lrow = tid >> 1;
    const int lhalf = tid & 1;
    const __half* ap = A + (long long)(m0 + lrow) * lda + lhalf * 32;
    const __half* bp = B + (long long)(n0 + lrow) * ldb + lhalf * 32;
    const uint32_t aSt = sbase + lrow * RSTR + lhalf * 64;
    const uint32_t bSt = sbase + TILEB + lrow * RSTR + lhalf * 64;

    // ---- warp mapping: 8 warps, 64x32 each ----
    const int wm = (wid & 1) * 64;
    const int wn = (wid >> 1) * 32;
    const int qr = lane >> 2, qc = lane & 3;
    uint32_t aF[4], bF[2];
    #pragma unroll
    for (int mi = 0; mi < 4; mi++)
        aF[mi] = sbase + (wm + mi * 16 + (lane & 15)) * RSTR + (lane >> 4) * 16;
    #pragma unroll
    for (int nt = 0; nt < 2; nt++)
        bF[nt] = sbase + TILEB +
                 (wn + nt * 16 + (lane & 7) + ((lane >> 4) << 3)) * RSTR +
                 ((lane >> 3) & 1) * 16;

    float acc[4][4][4];
    #pragma unroll
    for (int mi = 0; mi < 4; mi++)
        #pragma unroll
        for (int nj = 0; nj < 4; nj++)
            #pragma unroll
            for (int j = 0; j < 4; j++) acc[mi][nj][j] = 0.f;

    // ---- prologue: tiles 0,1 -> stages 0,1 (fresh empty barriers: no wait) ----
    #pragma unroll
    for (int i = 0; i < 4; i++) CPA16(aSt + i * 16, ap + i * 8);
    #pragma unroll
    for (int i = 0; i < 4; i++) CPA16(bSt + i * 16, bp + i * 8);
    CPA_MBAR_ARRIVE(mb + 0 * 8);
    if (NK > 1) {
        #pragma unroll
        for (int i = 0; i < 4; i++) CPA16(aSt + BUFB + i * 16, ap + 64 + i * 8);
        #pragma unroll
        for (int i = 0; i < 4; i++) CPA16(bSt + BUFB + i * 16, bp + 64 + i * 8);
        CPA_MBAR_ARRIVE(mb + 1 * 8);
    }

    // cursors: consumer (sc,pc) starts (0,0); producer (sp,pp) starts (2,1)
    int sc = 0, pc = 0;
    int sp = 2, pp = 1;
    for (int k = 0; k < NK; k++) {
        // wait data for stage sc, compute, release stage
        MBAR_WAIT(mb + sc * 8, pc);
        const uint32_t bo = sc * BUFB;
        #pragma unroll
        for (int s = 0; s < 4; s++) {
            uint32_t afr[4][4];
            #pragma unroll
            for (int mi = 0; mi < 4; mi++)
                LDM4(afr[mi][0], afr[mi][1], afr[mi][2], afr[mi][3],
                     aF[mi] + bo + s * 32);
            uint32_t bfr[4][2];
            #pragma unroll
            for (int nt = 0; nt < 2; nt++) {
                uint32_t t0, t1, t2, t3;
                LDM4(t0, t1, t2, t3, bF[nt] + bo + s * 32);
                bfr[nt * 2][0] = t0;     bfr[nt * 2][1] = t1;
                bfr[nt * 2 + 1][0] = t2; bfr[nt * 2 + 1][1] = t3;
            }
            #pragma unroll
            for (int mi = 0; mi < 4; mi++)
                #pragma unroll
                for (int nj = 0; nj < 4; nj++)
                    mma_f16(acc[mi][nj], afr[mi], bfr[nj]);
        }
        MBAR_ARRIVE(mb + 24 + sc * 8);
        if (++sc == 3) { sc = 0; pc ^= 1; }

        // prefetch tile k+2 into stage sp (emptied at iter k-1: slack ~1 k-tile)
        if (k + 2 < NK) {
            MBAR_WAIT(mb + 24 + sp * 8, pp);
            const int k0 = (k + 2) * 64;
            const uint32_t nb = sp * BUFB;
            #pragma unroll
            for (int i = 0; i < 4; i++) CPA16(aSt + nb + i * 16, ap + k0 + i * 8);
            #pragma unroll
            for (int i = 0; i < 4; i++) CPA16(bSt + nb + i * 16, bp + k0 + i * 8);
            CPA_MBAR_ARRIVE(mb + sp * 8);
            if (++sp == 3) { sp = 0; pp ^= 1; }
        }
    }

    // ---- epilogue: direct stores (no smem reuse -> no barrier needed) ----
    #pragma unroll
    for (int mi = 0; mi < 4; mi++) {
        #pragma unroll
        for (int h = 0; h < 2; h++) {
            const long long gm = m0 + wm + mi * 16 + qr + h * 8;
            float bm = 0.f;
            if (MG3) { if (biasM) bm = bias[gm]; }
            #pragma unroll
            for (int nj = 0; nj < 4; nj++) {
                const int gn = n0 + wn + nj * 8 + qc * 2;
                float vx = acc[mi][nj][h * 2 + 0] * scale;
                float vy = acc[mi][nj][h * 2 + 1] * scale;
                if (MG3) {
                    if (biasM) { vx += bm; vy += bm; }
                    else { const float2 bb = *(const float2*)(bias + gn); vx += bb.x; vy += bb.y; }
                } else if (BN_) {
                    const float2 bb = *(const float2*)(bias + gn); vx += bb.x; vy += bb.y;
                }
                if (ADD_) {
                    const float2 ad = *(const float2*)(Add + gm * ldc + gn);
                    vx += ad.x; vy += ad.y;
                }
                if (HOUT) {
                    __half* Co = (__half*)Csel + (MG3 ? 0ll : (long long)blockIdx.z * sC);
                    *(half2*)(Co + gm * ldc + gn) = __floats2half2_rn(vx, vy);
                } else {
                    float* Co = (float*)Csel + (MG3 ? 0ll : (long long)blockIdx.z * sC);
                    *(float2*)(Co + gm * ldc + gn) = make_float2(vx, vy);
                }
            }
        }
    }
}

// One fused fp32->fp16 conversion over all six tensors (grid-stride, 8 elems/iter)
#define ACT8 (Mtot * Cdim / 8)          // 1048576
#define W8   (Cdim * Cdim / 8)          // 131072
#define TOT8 (2 * ACT8 + 4 * W8)        // 2621440
__global__ __launch_bounds__(256)
void cvt_all(const float* __restrict__ x,  const float* __restrict__ ce,
             const float* __restrict__ Wq, const float* __restrict__ Wk,
             const float* __restrict__ Wv, const float* __restrict__ Wo,
             __half* __restrict__ xh,  __half* __restrict__ ceh,
             __half* __restrict__ Wqh, __half* __restrict__ Wkh,
             __half* __restrict__ Wvh, __half* __restrict__ Woh)
{
    for (int i = blockIdx.x * 256 + threadIdx.x; i < TOT8; i += gridDim.x * 256) {
        const float* s;
        __half* d;
        int j = i;
        if (j < ACT8)                 { s = x;  d = xh;  }
        else if ((j -= ACT8) < ACT8)  { s = ce; d = ceh; }
        else if ((j -= ACT8) < W8)    { s = Wq; d = Wqh; }
        else if ((j -= W8) < W8)      { s = Wk; d = Wkh; }
        else if ((j -= W8) < W8)      { s = Wv; d = Wvh; }
        else                          { j -= W8; s = Wo; d = Woh; }
        const float4 a = ((const float4*)s)[2 * j];
        const float4 b = ((const float4*)s)[2 * j + 1];
        uint4 o;
        half2 h;
        h = __floats2half2_rn(a.x, a.y); o.x = *(uint32_t*)&h;
        h = __floats2half2_rn(a.z, a.w); o.y = *(uint32_t*)&h;
        h = __floats2half2_rn(b.x, b.y); o.z = *(uint32_t*)&h;
        h = __floats2half2_rn(b.z, b.w); o.w = *(uint32_t*)&h;
        ((uint4*)d)[j] = o;
    }
}

// softmax over rows of 2048 halfs; 256 threads, 8 halfs/thread
__global__ __launch_bounds__(256)
void softmax_h(__half* __restrict__ S)
{
    uint4* p = (uint4*)(S + (long long)blockIdx.x * SKVdim);
    const int tid = threadIdx.x, wid = tid >> 5, lane = tid & 31;
    __shared__ float red[8];

    uint4 v = p[tid];
    float f[8];
    { float2 t;
      t = __half22float2(*(half2*)&v.x); f[0]=t.x; f[1]=t.y;
      t = __half22float2(*(half2*)&v.y); f[2]=t.x; f[3]=t.y;
      t = __half22float2(*(half2*)&v.z); f[4]=t.x; f[5]=t.y;
      t = __half22float2(*(half2*)&v.w); f[6]=t.x; f[7]=t.y; }

    float m = f[0];
    #pragma unroll
    for (int j = 1; j < 8; j++) m = fmaxf(m, f[j]);
    #pragma unroll
    for (int o = 16; o > 0; o >>= 1) m = fmaxf(m, __shfl_xor_sync(~0u, m, o));
    if (lane == 0) red[wid] = m;
    __syncthreads();
    m = red[0];
    #pragma unroll
    for (int w = 1; w < 8; w++) m = fmaxf(m, red[w]);
    __syncthreads();

    float s = 0.f;
    #pragma unroll
    for (int j = 0; j < 8; j++) { f[j] = __expf(f[j] - m); s += f[j]; }
    #pragma unroll
    for (int o = 16; o > 0; o >>= 1) s += __shfl_xor_sync(~0u, s, o);
    if (lane == 0) red[wid] = s;
    __syncthreads();
    s = red[0] + red[1] + red[2] + red[3] + red[4] + red[5] + red[6] + red[7];

    const float inv = 1.0f / s;
    half2 h;
    h = __floats2half2_rn(f[0]*inv, f[1]*inv); v.x = *(uint32_t*)&h;
    h = __floats2half2_rn(f[2]*inv, f[3]*inv); v.y = *(uint32_t*)&h;
    h = __floats2half2_rn(f[4]*inv, f[5]*inv); v.z = *(uint32_t*)&h;
    h = __floats2half2_rn(f[6]*inv, f[7]*inv); v.w = *(uint32_t*)&h;
    p[tid] = v;
}

extern "C" void kernel_launch(void* const* d_in, const int* in_sizes, int n_in,
                              void* d_out, int out_size)
{
    const float* x  = (const float*)d_in[0];
    const float* ce = (const float*)d_in[1];
    const float* Wq = (const float*)d_in[2];
    const float* bq = (const float*)d_in[3];
    const float* Wk = (const float*)d_in[4];
    const float* bk = (const float*)d_in[5];
    const float* Wv = (const float*)d_in[6];
    const float* bv = (const float*)d_in[7];
    const float* Wo = (const float*)d_in[8];
    const float* bo = (const float*)d_in[9];
    float* out = (float*)d_out;

    __half *xh, *ceh, *Wqh, *Wkh, *Wvh, *Woh, *Qh, *Kh, *Vth, *Sh, *Ath;
    cudaGetSymbolAddress((void**)&xh,  g_xh);
    cudaGetSymbolAddress((void**)&ceh, g_ceh);
    cudaGetSymbolAddress((void**)&Wqh, g_Wqh);
    cudaGetSymbolAddress((void**)&Wkh, g_Wkh);
    cudaGetSymbolAddress((void**)&Wvh, g_Wvh);
    cudaGetSymbolAddress((void**)&Woh, g_Woh);
    cudaGetSymbolAddress((void**)&Qh,  g_Qh);
    cudaGetSymbolAddress((void**)&Kh,  g_Kh);
    cudaGetSymbolAddress((void**)&Vth, g_Vth);
    cudaGetSymbolAddress((void**)&Sh,  g_Sh);
    cudaGetSymbolAddress((void**)&Ath, g_Ath);

    #define SETSM(KF) cudaFuncSetAttribute(KF, cudaFuncAttributeMaxDynamicSharedMemorySize, SMEM_BYTES)
    SETSM((gemm_k<true , false, false, true >));   // merged projections
    SETSM((gemm_k<true , false, false, false>));   // scores
    SETSM((gemm_k<true , false, true , false>));   // At (+residual)
    SETSM((gemm_k<false, true , false, false>));   // final

    dim3 blk(256);

    // 1: all dtype conversions in one grid-stride launch
    cvt_all<<<1184, 256>>>(x, ce, Wq, Wk, Wv, Wo, xh, ceh, Wqh, Wkh, Wvh, Woh);

    // 2: merged z=0 Qh=xh@Wqh^T+bq; z=1 Kh=ceh@Wkh^T+bk; z=2 Vth=Wvh@ceh^T+bv
    gemm_k<true,false,false,true><<<dim3(Cdim/128, Mtot/128, 3), blk, SMEM_BYTES>>>(
        xh,  Wqh, bq, Qh,
        ceh, Wkh, bk, Kh,
        Wvh, ceh, bv, Vth,
        nullptr, Cdim, Cdim, Cdim, Mtot, Cdim/64, 0,0,0,0, 1.0f);
    // 3: Sh = (Qh @ Kh^T) / 32
    gemm_k<true,false,false,false><<<dim3(SKVdim/128, SQdim/128, Bdim), blk, SMEM_BYTES>>>(
        Qh, Kh, nullptr, Sh,
        nullptr, nullptr, nullptr, nullptr,
        nullptr, nullptr, nullptr, nullptr,
        nullptr, Cdim, Cdim, SKVdim, 0, Cdim/64,
        (long long)SQdim*Cdim, (long long)SKVdim*Cdim, (long long)SQdim*SKVdim, 0, 0.03125f);
    // 4: Ph = softmax(Sh)
    softmax_h<<<Bdim * SQdim, 256>>>(Sh);
    // 5: Ath = Ph @ Vth^T + x   (half out)
    gemm_k<true,false,true,false><<<dim3(Cdim/128, SQdim/128, Bdim), blk, SMEM_BYTES>>>(
        Sh, Vth, nullptr, Ath,
        nullptr, nullptr, nullptr, nullptr,
        nullptr, nullptr, nullptr, nullptr,
        x, SKVdim, Mtot, Cdim, 0, SKVdim/64,
        (long long)SQdim*SKVdim, (long long)SKVdim, (long long)SQdim*Cdim,
        (long long)SQdim*Cdim, 1.0f);
    // 6: out = Ath @ Woh^T + bo  (float out)
    gemm_k<false,true,false,false><<<dim3(Cdim/128, Mtot/128, 1), blk, SMEM_BYTES>>>(
        Ath, Woh, bo, out,
        nullptr, nullptr, nullptr, nullptr,
        nullptr, nullptr, nullptr, nullptr,
        nullptr, Cdim, Cdim, Cdim, 0, Cdim/64, 0,0,0,0, 1.0f);
}